// round 6
// baseline (speedup 1.0000x reference)
#include <cuda_runtime.h>
#include <cuda_fp16.h>

#define NN 100000
#define EE 1600000
#define TILES ((NN + 127) / 128)

// ---------------- scratch (static __device__, no allocation) ----------------
// Per tile: 4 fp16 planes = 2 ping-pong sets x 2 K-chunks (k0-63, k64-127).
// Plane = 128 rows x 128B (64 fp16, SW128-swizzled within row) = 16KB.
// Set 0 = planes 0,1 ; set 1 = planes 2,3. Layer l reads set (l&1)^0 per schedule.
__device__ uint4 g_A[(size_t)TILES * 4 * 1024];   // ~51 MB
__device__ uint4 g_B[4 * 4 * 1024];               // per layer: 4 chunk planes, fp16
__device__ float g_st[(size_t)NN * 80];           // layer-4 GEMM out: s(40) | t(40)
__device__ int   g_deg[NN];
__device__ int   g_rp[NN + 1];
__device__ int   g_cur[NN];
__device__ int   g_col[EE];
__device__ int   g_bsum[256];

// ---------------- helpers ----------------
__device__ __forceinline__ int swz(int x) { return x ^ ((x >> 3) & 0x70); }

__device__ __forceinline__ uint2 pack_h4(float4 v) {
    __half2 a = __floats2half2_rn(v.x, v.y);
    __half2 b = __floats2half2_rn(v.z, v.w);
    uint2 r;
    r.x = *(unsigned*)&a;
    r.y = *(unsigned*)&b;
    return r;
}

__device__ __forceinline__ unsigned smem_u32(const void* p) {
    unsigned a;
    asm("{ .reg .u64 t; cvta.to.shared.u64 t, %1; cvt.u32.u64 %0, t; }" : "=r"(a) : "l"(p));
    return a;
}
__device__ __forceinline__ void cp16(unsigned s, const void* g) {
    asm volatile("cp.async.cg.shared.global [%0], [%1], 16;" :: "r"(s), "l"(g));
}
__device__ __forceinline__ void cp_commit() { asm volatile("cp.async.commit_group;"); }
__device__ __forceinline__ void cp_wait0() { asm volatile("cp.async.wait_group 0;"); }
__device__ __forceinline__ void cp_wait1() { asm volatile("cp.async.wait_group 1;"); }

__device__ __forceinline__ void ldm_x4(unsigned* r, unsigned addr) {
    asm volatile("ldmatrix.sync.aligned.m8n8.x4.shared.b16 {%0,%1,%2,%3}, [%4];"
                 : "=r"(r[0]), "=r"(r[1]), "=r"(r[2]), "=r"(r[3]) : "r"(addr));
}
__device__ __forceinline__ void mma_f16(float* d, const unsigned* a, unsigned b0, unsigned b1) {
    asm volatile(
        "mma.sync.aligned.m16n8k16.row.col.f32.f16.f16.f32 "
        "{%0,%1,%2,%3}, {%4,%5,%6,%7}, {%8,%9}, {%0,%1,%2,%3};"
        : "+f"(d[0]), "+f"(d[1]), "+f"(d[2]), "+f"(d[3])
        : "r"(a[0]), "r"(a[1]), "r"(a[2]), "r"(a[3]), "r"(b0), "r"(b1));
}

// one K=64 chunk of MMAs: A plane at Ap, B plane at Bp (both smem, swizzled)
__device__ __forceinline__ void mma_chunk(float acc[4][4][4], unsigned Ap, unsigned Bp,
                                          int arow, int brow, int lane) {
#pragma unroll
    for (int ks = 0; ks < 4; ks++) {
        unsigned afr[4][4];
        {
            int seg = ks * 2 + (lane >> 4);
            int inner = swz(((arow & 7) << 7) + seg * 16);
#pragma unroll
            for (int mt = 0; mt < 4; mt++)
                ldm_x4(afr[mt], Ap + (unsigned)((((arow >> 3) + 2 * mt) << 10) + inner));
        }
        unsigned bfr[2][4];
        {
            int seg = ks * 2 + ((lane >> 3) & 1);
            int inner = swz(((brow & 7) << 7) + seg * 16);
#pragma unroll
            for (int nb = 0; nb < 2; nb++)
                ldm_x4(bfr[nb], Bp + (unsigned)((((brow >> 3) + 2 * nb) << 10) + inner));
        }
#pragma unroll
        for (int mt = 0; mt < 4; mt++)
#pragma unroll
            for (int nt = 0; nt < 4; nt++)
                mma_f16(acc[mt][nt], afr[mt],
                        bfr[nt >> 1][(nt & 1) * 2], bfr[nt >> 1][(nt & 1) * 2 + 1]);
    }
}

// ---------------- prep: x -> fp16 planes set 0; also zero deg ----------------
__global__ void k_prep_x(const float* __restrict__ x, int n) {
    int idx = blockIdx.x * 256 + threadIdx.x;
    if (idx < n) g_deg[idx] = 0;
    if (idx >= n * 32) return;
    int node = idx >> 5, k = (idx & 31) << 2;
    float4 v = *(const float4*)(x + (size_t)node * 128 + k);
    uint2 q = pack_h4(v);
    int tile = node >> 7, r = node & 127, chunk = k >> 6, kb = (k & 63) << 1;
    char* base = (char*)g_A + ((size_t)tile * 4 + chunk) * 16384;   // set 0
    int off = ((r >> 3) << 10) + swz(((r & 7) << 7) + kb);
    *(uint2*)(base + off) = q;
}

// ---------------- prep: all weights -> fp16 planes ----------------
__global__ void k_prep_wall(const float* __restrict__ ws1, const float* __restrict__ wn1,
                            const float* __restrict__ ws2, const float* __restrict__ wn2,
                            const float* __restrict__ ws3, const float* __restrict__ wn3,
                            const float* __restrict__ ws4, const float* __restrict__ wn4) {
    int layer = blockIdx.y;
    int idx = blockIdx.x * 256 + threadIdx.x;   // 0..4095
    if (idx >= 4096) return;
    int f = idx >> 5, k = (idx & 31) << 2;
    int kb = (k & 63) << 1;
    int off = ((f >> 3) << 10) + swz(((f & 7) << 7) + kb);
    if (layer < 3) {
        const float* ws = (layer == 0) ? ws1 : (layer == 1) ? ws2 : ws3;
        const float* wn = (layer == 0) ? wn1 : (layer == 1) ? wn2 : wn3;
        float4 vs = *(const float4*)(ws + (size_t)f * 128 + k);
        float4 vn = *(const float4*)(wn + (size_t)f * 128 + k);
        int chunk = k >> 6;
        char* b0 = (char*)g_B + ((size_t)layer * 4 + chunk) * 16384;
        char* b1 = (char*)g_B + ((size_t)layer * 4 + chunk + 2) * 16384;
        *(uint2*)(b0 + off) = pack_h4(vs);
        *(uint2*)(b1 + off) = pack_h4(vn);
    } else {
        float4 v = make_float4(0.f, 0.f, 0.f, 0.f);
        if (f < 40) v = *(const float4*)(ws4 + (size_t)f * 128 + k);
        else if (f < 80) v = *(const float4*)(wn4 + (size_t)(f - 40) * 128 + k);
        int chunk = k >> 6;
        char* b0 = (char*)g_B + ((size_t)3 * 4 + chunk) * 16384;
        *(uint2*)(b0 + off) = pack_h4(v);
    }
}

// ---------------- CSR build ----------------
__global__ void k_count(const int* __restrict__ dst, int e) {
    int i = blockIdx.x * blockDim.x + threadIdx.x;
    if (i < e) atomicAdd(&g_deg[dst[i]], 1);
}
__global__ void k_scan1(int n) {
    __shared__ int s[512];
    int i = blockIdx.x * 512 + threadIdx.x;
    int v = (i < n) ? g_deg[i] : 0;
    s[threadIdx.x] = v;
    __syncthreads();
    for (int off = 1; off < 512; off <<= 1) {
        int t = (threadIdx.x >= off) ? s[threadIdx.x - off] : 0;
        __syncthreads();
        s[threadIdx.x] += t;
        __syncthreads();
    }
    if (i < n) g_rp[i] = s[threadIdx.x] - v;
    if (threadIdx.x == 511) g_bsum[blockIdx.x] = s[511];
}
__global__ void k_scan3b(int n, int e, int nb) {
    __shared__ int s[512];
    int tid = threadIdx.x, bid = blockIdx.x;
    s[tid] = (tid < nb && tid < bid) ? g_bsum[tid] : 0;
    __syncthreads();
    for (int off = 256; off >= 1; off >>= 1) {
        if (tid < off) s[tid] += s[tid + off];
        __syncthreads();
    }
    int offv = s[0];
    int i = bid * 512 + tid;
    if (i < n) {
        int r = g_rp[i] + offv;
        g_rp[i] = r;
        g_cur[i] = r;
    }
    if (i == 0) g_rp[n] = e;
}
__global__ void k_scatter(const int* __restrict__ src, const int* __restrict__ dst, int e) {
    int i = blockIdx.x * blockDim.x + threadIdx.x;
    if (i < e) {
        int d = dst[i];
        int p = atomicAdd(&g_cur[d], 1);
        g_col[p] = src[i];
    }
}

// ---------------- fused agg + GEMM (layers 1-3) ----------------
// smem: [0,32K) m planes (chunks 2,3) | [32K,64K) H0,H1 | [64K,96K) W0,W1
// Reads h planes from set hset; writes h' planes to set 1-hset.
__global__ __launch_bounds__(256, 2)
void k_fused(const uint4* __restrict__ Bw, const float* __restrict__ bias,
             int hset, int n) {
    extern __shared__ char smem[];
    const int tid = threadIdx.x, wid = tid >> 5, lane = tid & 31;
    const int mh = wid >> 2, nq = wid & 3;
    const size_t tile = blockIdx.x;
    const unsigned sbase = smem_u32(smem);

    const uint4* gH = g_A + (tile * 4 + (size_t)hset * 2) * 1024;

    // prologue: prefetch h chunks 0,1 and B chunks 0,1
    {
        unsigned dh = sbase + 32768u, dw = sbase + 65536u;
#pragma unroll
        for (int i = 0; i < 4; i++) cp16(dh + (tid + i * 256) * 16, gH + tid + i * 256);
#pragma unroll
        for (int i = 0; i < 4; i++) cp16(dw + (tid + i * 256) * 16, Bw + tid + i * 256);
        cp_commit();
#pragma unroll
        for (int i = 0; i < 4; i++) cp16(dh + 16384u + (tid + i * 256) * 16, gH + 1024 + tid + i * 256);
#pragma unroll
        for (int i = 0; i < 4; i++) cp16(dw + 16384u + (tid + i * 256) * 16, Bw + 1024 + tid + i * 256);
        cp_commit();
    }

    // gather phase: warp w handles nodes tile*128 + w*16 + [0,16)
    {
        const int chunk = lane >> 4, kb = (lane & 15) << 3;
        const char* Ab = (const char*)g_A;
        const int hs2 = hset * 2;
        for (int i = 0; i < 16; i++) {
            int node = (int)tile * 128 + wid * 16 + i;
            if (node >= n) break;
            int beg = g_rp[node], end = g_rp[node + 1];
            float4 acc = make_float4(0.f, 0.f, 0.f, 0.f);
            for (int e = beg; e < end; e += 4) {
                int i1 = min(e + 1, end - 1);
                int i2 = min(e + 2, end - 1);
                int i3 = min(e + 3, end - 1);
                int u0 = g_col[e], u1 = g_col[i1], u2 = g_col[i2], u3 = g_col[i3];
#define ROWADDR(u) (Ab + ((size_t)((u >> 7) * 4 + hs2 + chunk)) * 16384 + \
                    (((u & 127) >> 3) << 10) + swz((((u & 127) & 7) << 7) + kb))
                uint2 q0 = *(const uint2*)ROWADDR(u0);
                uint2 q1 = *(const uint2*)ROWADDR(u1);
                uint2 q2 = *(const uint2*)ROWADDR(u2);
                uint2 q3 = *(const uint2*)ROWADDR(u3);
#undef ROWADDR
#define ACC4(q) do { \
                float2 f0 = __half22float2(*(__half2*)&(q).x); \
                float2 f1 = __half22float2(*(__half2*)&(q).y); \
                acc.x += f0.x; acc.y += f0.y; acc.z += f1.x; acc.w += f1.y; } while (0)
                ACC4(q0);
                if (e + 1 < end) ACC4(q1);
                if (e + 2 < end) ACC4(q2);
                if (e + 3 < end) ACC4(q3);
#undef ACC4
            }
            float inv = 1.0f / (float)max(end - beg, 1);
            acc.x *= inv; acc.y *= inv; acc.z *= inv; acc.w *= inv;
            int r = node & 127;
            char* mp = smem + chunk * 16384;
            int off = ((r >> 3) << 10) + swz(((r & 7) << 7) + kb);
            *(uint2*)(mp + off) = pack_h4(acc);
        }
    }

    // MMA pipeline
    float acc[4][4][4];
#pragma unroll
    for (int a = 0; a < 4; a++)
#pragma unroll
        for (int b = 0; b < 4; b++)
#pragma unroll
            for (int c = 0; c < 4; c++) acc[a][b][c] = 0.f;

    const int arow = mh * 64 + (lane & 15);
    const int brow = nq * 32 + ((lane >> 4) << 3) + (lane & 7);
    const unsigned H0 = sbase + 32768u, H1 = sbase + 49152u;
    const unsigned W0 = sbase + 65536u, W1 = sbase + 81920u;
    const unsigned M0 = sbase, M1 = sbase + 16384u;

    cp_wait1();
    __syncthreads();
    mma_chunk(acc, H0, W0, arow, brow, lane);          // chunk 0: h x Ws[k0-63]
    __syncthreads();
    {   // B chunk 2 -> W0
        unsigned dw = sbase + 65536u;
#pragma unroll
        for (int i = 0; i < 4; i++) cp16(dw + (tid + i * 256) * 16, Bw + 2048 + tid + i * 256);
        cp_commit();
    }
    cp_wait1();
    __syncthreads();
    mma_chunk(acc, H1, W1, arow, brow, lane);          // chunk 1: h x Ws[k64-127]
    __syncthreads();
    {   // B chunk 3 -> W1
        unsigned dw = sbase + 81920u;
#pragma unroll
        for (int i = 0; i < 4; i++) cp16(dw + (tid + i * 256) * 16, Bw + 3072 + tid + i * 256);
        cp_commit();
    }
    cp_wait1();
    __syncthreads();
    mma_chunk(acc, M0, W0, arow, brow, lane);          // chunk 2: m x Wn[k0-63]
    __syncthreads();
    cp_wait0();
    __syncthreads();
    mma_chunk(acc, M1, W1, arow, brow, lane);          // chunk 3: m x Wn[k64-127]
    __syncthreads();

    // epilogue: bias + relu -> fp16 swizzled stage -> write set 1-hset planes
    const size_t base = tile * 128;
    const int rr = lane >> 2, cc = (lane & 3) * 2;
    __half* stg = (__half*)(smem + 32768);   // stride 132 halves (33792 B, fits in 64KB)
#pragma unroll
    for (int mt = 0; mt < 4; mt++)
#pragma unroll
        for (int nt = 0; nt < 4; nt++) {
            int r = mh * 64 + mt * 16 + rr;
            int col = nq * 32 + nt * 8 + cc;
            float bv0 = __ldg(bias + col), bv1 = __ldg(bias + col + 1);
            float v0 = fmaxf(acc[mt][nt][0] + bv0, 0.f);
            float v1 = fmaxf(acc[mt][nt][1] + bv1, 0.f);
            float v2 = fmaxf(acc[mt][nt][2] + bv0, 0.f);
            float v3 = fmaxf(acc[mt][nt][3] + bv1, 0.f);
            *(__half2*)(stg + r * 132 + col) = __floats2half2_rn(v0, v1);
            *(__half2*)(stg + (r + 8) * 132 + col) = __floats2half2_rn(v2, v3);
        }
    __syncthreads();
    const int ws2 = (1 - hset) * 2;
    for (int t = tid; t < 4096; t += 256) {
        int nn = t >> 5, g = t & 31;
        size_t gn = base + nn;
        if (gn < (size_t)n) {
            uint2 q = *(uint2*)(stg + nn * 132 + g * 4);
            int k0 = g * 4;
            int chunk = k0 >> 6, kb = (k0 & 63) << 1;
            char* bA = (char*)g_A + (tile * 4 + ws2 + chunk) * 16384;
            int off = ((nn >> 3) << 10) + swz(((nn & 7) << 7) + kb);
            *(uint2*)(bA + off) = q;
        }
    }
}

// ---------------- layer-4 GEMM: st[128 x 80] = h3[128 x 128] * [Ws4;Wn4]^T ----------------
__global__ __launch_bounds__(256, 2)
void k_gemm4(const uint4* __restrict__ Bw, float* __restrict__ out, int hset, int n) {
    extern __shared__ char smem[];
    const int tid = threadIdx.x, wid = tid >> 5, lane = tid & 31;
    const int mh = wid >> 2, nq = wid & 3;
    const size_t tile = blockIdx.x;
    const unsigned sbase = smem_u32(smem);

    const uint4* gAt = g_A + (tile * 4 + (size_t)hset * 2) * 1024;

    float acc[4][4][4];
#pragma unroll
    for (int a = 0; a < 4; a++)
#pragma unroll
        for (int b = 0; b < 4; b++)
#pragma unroll
            for (int c = 0; c < 4; c++) acc[a][b][c] = 0.f;

    const int arow = mh * 64 + (lane & 15);
    const int brow = nq * 32 + ((lane >> 4) << 3) + (lane & 7);

    // prefetch both chunks (A + B)
    {
        unsigned da = sbase, dw = sbase + 32768u;
#pragma unroll
        for (int i = 0; i < 4; i++) cp16(da + (tid + i * 256) * 16, gAt + tid + i * 256);
#pragma unroll
        for (int i = 0; i < 4; i++) cp16(dw + (tid + i * 256) * 16, Bw + tid + i * 256);
        cp_commit();
#pragma unroll
        for (int i = 0; i < 4; i++) cp16(da + 16384u + (tid + i * 256) * 16, gAt + 1024 + tid + i * 256);
#pragma unroll
        for (int i = 0; i < 4; i++) cp16(dw + 16384u + (tid + i * 256) * 16, Bw + 1024 + tid + i * 256);
        cp_commit();
    }

    cp_wait1();
    __syncthreads();
    mma_chunk(acc, sbase, sbase + 32768u, arow, brow, lane);
    cp_wait0();
    __syncthreads();
    mma_chunk(acc, sbase + 16384u, sbase + 49152u, arow, brow, lane);
    __syncthreads();

    // epilogue: fp32 stage (cols 0..79), coalesced store to g_st
    const size_t base = tile * 128;
    const int rr = lane >> 2, cc = (lane & 3) * 2;
    float* stage = (float*)smem;   // stride 84 floats: 128*84*4 = 43008 <= 64KB
#pragma unroll
    for (int mt = 0; mt < 4; mt++)
#pragma unroll
        for (int nt = 0; nt < 4; nt++) {
            int col = nq * 32 + nt * 8 + cc;
            if (col < 80) {
                int r = mh * 64 + mt * 16 + rr;
                stage[r * 84 + col] = acc[mt][nt][0];
                stage[r * 84 + col + 1] = acc[mt][nt][1];
                stage[(r + 8) * 84 + col] = acc[mt][nt][2];
                stage[(r + 8) * 84 + col + 1] = acc[mt][nt][3];
            }
        }
    __syncthreads();
    for (int t = tid; t < 128 * 20; t += 256) {
        int nn = t / 20, c4 = t % 20;
        size_t gn = base + nn;
        if (gn < (size_t)n)
            *(float4*)(out + gn * 80 + c4 * 4) = *(float4*)(stage + nn * 84 + c4 * 4);
    }
}

// ---------------- final aggregation: out[v] = s[v] + mean_t + b ----------------
__global__ __launch_bounds__(256)
void k_aggf(const float* __restrict__ st, const float* __restrict__ b,
            float* __restrict__ out, int n) {
    int w = (blockIdx.x * 256 + threadIdx.x) >> 5;
    int lane = threadIdx.x & 31;
    if (w >= n) return;
    int beg = g_rp[w], end = g_rp[w + 1];

    float a0 = 0.f, a1 = 0.f;
    for (int e = beg; e < end; e += 2) {
        int i1 = min(e + 1, end - 1);
        int u0 = g_col[e], u1 = g_col[i1];
        const float* t0 = st + (size_t)u0 * 80 + 40;
        const float* t1 = st + (size_t)u1 * 80 + 40;
        a0 += t0[lane];
        if (lane < 8) a1 += t0[32 + lane];
        if (e + 1 < end) {
            a0 += t1[lane];
            if (lane < 8) a1 += t1[32 + lane];
        }
    }
    float inv = 1.0f / (float)max(end - beg, 1);
    const float* sp = st + (size_t)w * 80;
    out[(size_t)w * 40 + lane] = fmaf(a0, inv, sp[lane] + __ldg(b + lane));
    if (lane < 8) {
        int f = 32 + lane;
        out[(size_t)w * 40 + f] = fmaf(a1, inv, sp[f] + __ldg(b + f));
    }
}

// ---------------- launch ----------------
extern "C" void kernel_launch(void* const* d_in, const int* in_sizes, int n_in,
                              void* d_out, int out_size) {
    const float* x   = (const float*)d_in[0];
    const int*   src = (const int*)d_in[1];
    const int*   dst = (const int*)d_in[2];
    const float* ws1 = (const float*)d_in[3];
    const float* wn1 = (const float*)d_in[4];
    const float* b1  = (const float*)d_in[5];
    const float* ws2 = (const float*)d_in[6];
    const float* wn2 = (const float*)d_in[7];
    const float* b2  = (const float*)d_in[8];
    const float* ws3 = (const float*)d_in[9];
    const float* wn3 = (const float*)d_in[10];
    const float* b3  = (const float*)d_in[11];
    const float* ws4 = (const float*)d_in[12];
    const float* wn4 = (const float*)d_in[13];
    const float* b4  = (const float*)d_in[14];

    const int n = in_sizes[0] / 128;
    const int E = in_sizes[1];
    const int tiles = (n + 127) / 128;

    const int SMEM_F = 96 * 1024;
    const int SMEM_4 = 64 * 1024;
    cudaFuncSetAttribute(k_fused, cudaFuncAttributeMaxDynamicSharedMemorySize, SMEM_F);
    cudaFuncSetAttribute(k_gemm4, cudaFuncAttributeMaxDynamicSharedMemorySize, SMEM_4);

    float* pst;
    uint4* pB;
    cudaGetSymbolAddress((void**)&pst, g_st);
    cudaGetSymbolAddress((void**)&pB, g_B);

    // preps (prep_x also zeroes deg)
    k_prep_x<<<(n * 32 + 255) / 256, 256>>>(x, n);
    k_prep_wall<<<dim3(16, 4), 256>>>(ws1, wn1, ws2, wn2, ws3, wn3, ws4, wn4);

    // CSR build (by dst)
    k_count<<<(E + 255) / 256, 256>>>(dst, E);
    int nb = (n + 511) / 512;
    k_scan1<<<nb, 512>>>(n);
    k_scan3b<<<nb, 512>>>(n, E, nb);
    k_scatter<<<(E + 255) / 256, 256>>>(src, dst, E);

    // L1: read set0, write set1 ; L2: 1->0 ; L3: 0->1
    k_fused<<<tiles, 256, SMEM_F>>>(pB + 0 * 4096, b1, 0, n);
    k_fused<<<tiles, 256, SMEM_F>>>(pB + 1 * 4096, b2, 1, n);
    k_fused<<<tiles, 256, SMEM_F>>>(pB + 2 * 4096, b3, 0, n);
    // L4: GEMM on set1, then final gather -> d_out
    k_gemm4<<<tiles, 256, SMEM_4>>>(pB + 3 * 4096, pst, 1, n);
    k_aggf<<<(n + 7) / 8, 256>>>(pst, b4, (float*)d_out, n);
}

// round 7
// speedup vs baseline: 1.0513x; 1.0513x over previous
#include <cuda_runtime.h>
#include <cuda_fp16.h>

#define NN 100000
#define EE 1600000
#define TILES ((NN + 127) / 128)

// ---------------- scratch (static __device__, no allocation) ----------------
// Per tile: 4 fp16 planes (h:k0-63, h:k64-127, m:k0-63, m:k64-127).
// Plane = 128 rows x 128B (64 fp16, SW128-swizzled within row) = 16KB.
__device__ uint4 g_A[(size_t)TILES * 4 * 1024];   // ~51 MB
__device__ uint4 g_B[4 * 4 * 1024];               // per layer: 4 chunk planes, fp16
__device__ float g_st[(size_t)NN * 80];           // layer-4 GEMM out: s(40) | t(40)
__device__ int   g_deg[NN];
__device__ int   g_rp[NN + 1];
__device__ int   g_cur[NN];
__device__ int   g_col[EE];
__device__ int   g_bsum[256];

// ---------------- helpers ----------------
__device__ __forceinline__ int swz(int x) { return x ^ ((x >> 3) & 0x70); }

__device__ __forceinline__ uint2 pack_h4(float4 v) {
    __half2 a = __floats2half2_rn(v.x, v.y);
    __half2 b = __floats2half2_rn(v.z, v.w);
    uint2 r;
    r.x = *(unsigned*)&a;
    r.y = *(unsigned*)&b;
    return r;
}

__device__ __forceinline__ unsigned smem_u32(const void* p) {
    unsigned a;
    asm("{ .reg .u64 t; cvta.to.shared.u64 t, %1; cvt.u32.u64 %0, t; }" : "=r"(a) : "l"(p));
    return a;
}
__device__ __forceinline__ void cp16(unsigned s, const void* g) {
    asm volatile("cp.async.cg.shared.global [%0], [%1], 16;" :: "r"(s), "l"(g));
}
__device__ __forceinline__ void cp_commit() { asm volatile("cp.async.commit_group;"); }
__device__ __forceinline__ void cp_wait0() { asm volatile("cp.async.wait_group 0;"); }
__device__ __forceinline__ void cp_wait1() { asm volatile("cp.async.wait_group 1;"); }

__device__ __forceinline__ void ldm_x4(unsigned* r, unsigned addr) {
    asm volatile("ldmatrix.sync.aligned.m8n8.x4.shared.b16 {%0,%1,%2,%3}, [%4];"
                 : "=r"(r[0]), "=r"(r[1]), "=r"(r[2]), "=r"(r[3]) : "r"(addr));
}
__device__ __forceinline__ void mma_f16(float* d, const unsigned* a, unsigned b0, unsigned b1) {
    asm volatile(
        "mma.sync.aligned.m16n8k16.row.col.f32.f16.f16.f32 "
        "{%0,%1,%2,%3}, {%4,%5,%6,%7}, {%8,%9}, {%0,%1,%2,%3};"
        : "+f"(d[0]), "+f"(d[1]), "+f"(d[2]), "+f"(d[3])
        : "r"(a[0]), "r"(a[1]), "r"(a[2]), "r"(a[3]), "r"(b0), "r"(b1));
}

// ---------------- prep: x -> fp16 planes (chunks 0,1); also zero deg ----------------
__global__ void k_prep_x(const float* __restrict__ x, int n) {
    int idx = blockIdx.x * 256 + threadIdx.x;
    if (idx < n) g_deg[idx] = 0;
    if (idx >= n * 32) return;
    int node = idx >> 5, k = (idx & 31) << 2;
    float4 v = *(const float4*)(x + (size_t)node * 128 + k);
    uint2 q = pack_h4(v);
    int tile = node >> 7, r = node & 127, chunk = k >> 6, kb = (k & 63) << 1;
    char* base = (char*)g_A + ((size_t)tile * 4 + chunk) * 16384;
    int off = ((r >> 3) << 10) + swz(((r & 7) << 7) + kb);
    *(uint2*)(base + off) = q;
}

// ---------------- prep: all weights -> fp16 planes ----------------
__global__ void k_prep_wall(const float* __restrict__ ws1, const float* __restrict__ wn1,
                            const float* __restrict__ ws2, const float* __restrict__ wn2,
                            const float* __restrict__ ws3, const float* __restrict__ wn3,
                            const float* __restrict__ ws4, const float* __restrict__ wn4) {
    int layer = blockIdx.y;
    int idx = blockIdx.x * 256 + threadIdx.x;   // 0..4095
    if (idx >= 4096) return;
    int f = idx >> 5, k = (idx & 31) << 2;
    int kb = (k & 63) << 1;
    int off = ((f >> 3) << 10) + swz(((f & 7) << 7) + kb);
    if (layer < 3) {
        const float* ws = (layer == 0) ? ws1 : (layer == 1) ? ws2 : ws3;
        const float* wn = (layer == 0) ? wn1 : (layer == 1) ? wn2 : wn3;
        float4 vs = *(const float4*)(ws + (size_t)f * 128 + k);
        float4 vn = *(const float4*)(wn + (size_t)f * 128 + k);
        int chunk = k >> 6;
        char* b0 = (char*)g_B + ((size_t)layer * 4 + chunk) * 16384;
        char* b1 = (char*)g_B + ((size_t)layer * 4 + chunk + 2) * 16384;
        *(uint2*)(b0 + off) = pack_h4(vs);
        *(uint2*)(b1 + off) = pack_h4(vn);
    } else {
        float4 v = make_float4(0.f, 0.f, 0.f, 0.f);
        if (f < 40) v = *(const float4*)(ws4 + (size_t)f * 128 + k);
        else if (f < 80) v = *(const float4*)(wn4 + (size_t)(f - 40) * 128 + k);
        int chunk = k >> 6;
        char* b0 = (char*)g_B + ((size_t)3 * 4 + chunk) * 16384;
        *(uint2*)(b0 + off) = pack_h4(v);
    }
}

// ---------------- CSR build ----------------
__global__ void k_count(const int* __restrict__ dst, int e) {
    int i = blockIdx.x * blockDim.x + threadIdx.x;
    if (i < e) atomicAdd(&g_deg[dst[i]], 1);
}
__global__ void k_scan1(int n) {
    __shared__ int s[512];
    int i = blockIdx.x * 512 + threadIdx.x;
    int v = (i < n) ? g_deg[i] : 0;
    s[threadIdx.x] = v;
    __syncthreads();
    for (int off = 1; off < 512; off <<= 1) {
        int t = (threadIdx.x >= off) ? s[threadIdx.x - off] : 0;
        __syncthreads();
        s[threadIdx.x] += t;
        __syncthreads();
    }
    if (i < n) g_rp[i] = s[threadIdx.x] - v;
    if (threadIdx.x == 511) g_bsum[blockIdx.x] = s[511];
}
__global__ void k_scan3b(int n, int e, int nb) {
    __shared__ int s[512];
    int tid = threadIdx.x, bid = blockIdx.x;
    s[tid] = (tid < nb && tid < bid) ? g_bsum[tid] : 0;
    __syncthreads();
    for (int off = 256; off >= 1; off >>= 1) {
        if (tid < off) s[tid] += s[tid + off];
        __syncthreads();
    }
    int offv = s[0];
    int i = bid * 512 + tid;
    if (i < n) {
        int r = g_rp[i] + offv;
        g_rp[i] = r;
        g_cur[i] = r;
    }
    if (i == 0) g_rp[n] = e;
}
__global__ void k_scatter(const int* __restrict__ src, const int* __restrict__ dst, int e) {
    int i = blockIdx.x * blockDim.x + threadIdx.x;
    if (i < e) {
        int d = dst[i];
        int p = atomicAdd(&g_cur[d], 1);
        g_col[p] = src[i];
    }
}

// ---------------- aggregation: m[v] = mean_in h[src]; fp16 planes -> m planes ----------------
// One warp per node; two edges per iteration (half-warp each), 16B loads, 4-deep unroll.
__global__ __launch_bounds__(256)
void k_aggm(int n) {
    int w = (blockIdx.x * 256 + threadIdx.x) >> 5;
    int lane = threadIdx.x & 31;
    if (w >= n) return;
    int beg = g_rp[w], end = g_rp[w + 1];

    const int half = lane >> 4, l = lane & 15;
    const int chunk = l >> 3, kb = (l & 7) << 4;    // 16 bytes = 8 fp16 features per lane
    const char* Ab = (const char*)g_A;

    float acc[8];
#pragma unroll
    for (int i = 0; i < 8; i++) acc[i] = 0.f;

    for (int e = beg; e < end; e += 8) {
#pragma unroll
        for (int j = 0; j < 4; j++) {
            int idx = e + 2 * j + half;
            int cidx = min(idx, end - 1);
            int u = g_col[cidx];
            const uint4* p = (const uint4*)(Ab +
                ((size_t)((u >> 7) * 4 + chunk)) * 16384 +
                (((u & 127) >> 3) << 10) + swz((((u & 127) & 7) << 7) + kb));
            uint4 q = *p;
            if (idx < end) {
                float2 f0 = __half22float2(*(__half2*)&q.x);
                float2 f1 = __half22float2(*(__half2*)&q.y);
                float2 f2 = __half22float2(*(__half2*)&q.z);
                float2 f3 = __half22float2(*(__half2*)&q.w);
                acc[0] += f0.x; acc[1] += f0.y; acc[2] += f1.x; acc[3] += f1.y;
                acc[4] += f2.x; acc[5] += f2.y; acc[6] += f3.x; acc[7] += f3.y;
            }
        }
    }
    // fold the two half-warps
#pragma unroll
    for (int i = 0; i < 8; i++) acc[i] += __shfl_xor_sync(0xffffffffu, acc[i], 16);

    if (lane < 16) {
        float inv = 1.0f / (float)max(end - beg, 1);
#pragma unroll
        for (int i = 0; i < 8; i++) acc[i] *= inv;
        uint4 q;
        __half2 h0 = __floats2half2_rn(acc[0], acc[1]);
        __half2 h1 = __floats2half2_rn(acc[2], acc[3]);
        __half2 h2 = __floats2half2_rn(acc[4], acc[5]);
        __half2 h3 = __floats2half2_rn(acc[6], acc[7]);
        q.x = *(unsigned*)&h0; q.y = *(unsigned*)&h1;
        q.z = *(unsigned*)&h2; q.w = *(unsigned*)&h3;
        int tile = w >> 7, r = w & 127;
        char* base = (char*)g_A + ((size_t)tile * 4 + 2 + chunk) * 16384;
        int off = ((r >> 3) << 10) + swz(((r & 7) << 7) + kb);
        *(uint4*)(base + off) = q;
    }
}

// ---------------- fp16 mma GEMM: D[128 x 128] = A[128 x 64*NC] * B[128 x 64*NC]^T ----------------
__device__ __forceinline__ void prefetch_chunk(char* smembase, int c, const uint4* gAt,
                                               const uint4* __restrict__ Bw, int tid) {
    char* buf = smembase + (c & 1) * 32768;
    const uint4* sa = gAt + (size_t)c * 1024;
    unsigned da = smem_u32(buf);
#pragma unroll
    for (int i = 0; i < 4; i++) cp16(da + (tid + i * 256) * 16, sa + tid + i * 256);
    const uint4* sb = Bw + (size_t)c * 1024;
    unsigned db = smem_u32(buf + 16384);
#pragma unroll
    for (int i = 0; i < 4; i++) cp16(db + (tid + i * 256) * 16, sb + tid + i * 256);
    cp_commit();
}

template <int NC, bool FINAL>
__global__ __launch_bounds__(256, 2)
void k_gemm_mma(const uint4* __restrict__ Bw, const float* __restrict__ bias,
                float* __restrict__ out, int n) {
    extern __shared__ char smem[];
    const int tid = threadIdx.x, wid = tid >> 5, lane = tid & 31;
    const int mh = wid >> 2, nq = wid & 3;
    const size_t tile = blockIdx.x;
    const unsigned sbase = smem_u32(smem);

    const uint4* gAt = g_A + tile * 4 * 1024;

    float acc[4][4][4];
#pragma unroll
    for (int a = 0; a < 4; a++)
#pragma unroll
        for (int b = 0; b < 4; b++)
#pragma unroll
            for (int c = 0; c < 4; c++) acc[a][b][c] = 0.f;

    const int arow = mh * 64 + (lane & 15);
    const int brow = nq * 32 + ((lane >> 4) << 3) + (lane & 7);

    prefetch_chunk(smem, 0, gAt, Bw, tid);

#pragma unroll 1
    for (int c = 0; c < NC; c++) {
        if (c < NC - 1) { prefetch_chunk(smem, c + 1, gAt, Bw, tid); cp_wait1(); }
        else cp_wait0();
        __syncthreads();

        unsigned bufu = sbase + (unsigned)((c & 1) * 32768);
        unsigned Ap = bufu, Bp = bufu + 16384u;
#pragma unroll
        for (int ks = 0; ks < 4; ks++) {
            unsigned afr[4][4];
            {
                int seg = ks * 2 + (lane >> 4);
                int inner = swz(((arow & 7) << 7) + seg * 16);
#pragma unroll
                for (int mt = 0; mt < 4; mt++)
                    ldm_x4(afr[mt], Ap + (unsigned)((((arow >> 3) + 2 * mt) << 10) + inner));
            }
            unsigned bfr[2][4];
            {
                int seg = ks * 2 + ((lane >> 3) & 1);
                int inner = swz(((brow & 7) << 7) + seg * 16);
#pragma unroll
                for (int nb = 0; nb < 2; nb++)
                    ldm_x4(bfr[nb], Bp + (unsigned)((((brow >> 3) + 2 * nb) << 10) + inner));
            }
#pragma unroll
            for (int mt = 0; mt < 4; mt++)
#pragma unroll
                for (int nt = 0; nt < 4; nt++)
                    mma_f16(acc[mt][nt], afr[mt],
                            bfr[nt >> 1][(nt & 1) * 2], bfr[nt >> 1][(nt & 1) * 2 + 1]);
        }
        __syncthreads();
    }

    // -------- epilogue --------
    const size_t base = tile * 128;
    const int rr = lane >> 2, cc = (lane & 3) * 2;

    if (FINAL) {
        float* stage = (float*)smem;   // stride 84 floats, cols 0..79
#pragma unroll
        for (int mt = 0; mt < 4; mt++)
#pragma unroll
            for (int nt = 0; nt < 4; nt++) {
                int col = nq * 32 + nt * 8 + cc;
                if (col < 80) {
                    int r = mh * 64 + mt * 16 + rr;
                    stage[r * 84 + col] = acc[mt][nt][0];
                    stage[r * 84 + col + 1] = acc[mt][nt][1];
                    stage[(r + 8) * 84 + col] = acc[mt][nt][2];
                    stage[(r + 8) * 84 + col + 1] = acc[mt][nt][3];
                }
            }
        __syncthreads();
        for (int t = tid; t < 128 * 20; t += 256) {
            int nn = t / 20, c4 = t % 20;
            size_t gn = base + nn;
            if (gn < (size_t)n)
                *(float4*)(out + gn * 80 + c4 * 4) = *(float4*)(stage + nn * 84 + c4 * 4);
        }
    } else {
        __half* stg = (__half*)smem;   // stride 132 halves
#pragma unroll
        for (int mt = 0; mt < 4; mt++)
#pragma unroll
            for (int nt = 0; nt < 4; nt++) {
                int r = mh * 64 + mt * 16 + rr;
                int col = nq * 32 + nt * 8 + cc;
                float bv0 = __ldg(bias + col), bv1 = __ldg(bias + col + 1);
                float v0 = fmaxf(acc[mt][nt][0] + bv0, 0.f);
                float v1 = fmaxf(acc[mt][nt][1] + bv1, 0.f);
                float v2 = fmaxf(acc[mt][nt][2] + bv0, 0.f);
                float v3 = fmaxf(acc[mt][nt][3] + bv1, 0.f);
                *(__half2*)(stg + r * 132 + col) = __floats2half2_rn(v0, v1);
                *(__half2*)(stg + (r + 8) * 132 + col) = __floats2half2_rn(v2, v3);
            }
        __syncthreads();
        for (int t = tid; t < 4096; t += 256) {
            int nn = t >> 5, g = t & 31;
            size_t gn = base + nn;
            if (gn < (size_t)n) {
                uint2 q = *(uint2*)(stg + nn * 132 + g * 4);
                int k0 = g * 4;
                int chunk = k0 >> 6, kb = (k0 & 63) << 1;
                char* bA = (char*)g_A + (tile * 4 + chunk) * 16384;
                int off = ((nn >> 3) << 10) + swz(((nn & 7) << 7) + kb);
                *(uint2*)(bA + off) = q;
            }
        }
    }
}

// ---------------- final aggregation: out[v] = s[v] + mean_t + b ----------------
// 3 edges per warp-iteration: lanes grouped in 10s, float4 loads (t = 40 floats).
__global__ __launch_bounds__(256)
void k_aggf(const float* __restrict__ st, const float* __restrict__ b,
            float* __restrict__ out, int n) {
    int w = (blockIdx.x * 256 + threadIdx.x) >> 5;
    int lane = threadIdx.x & 31;
    if (w >= n) return;
    int beg = g_rp[w], end = g_rp[w + 1];

    const int grp = lane / 10;          // 0,1,2 active; lane 30,31 -> grp 3 idle
    const int sub = lane - grp * 10;
    const bool active = lane < 30;

    float4 acc = make_float4(0.f, 0.f, 0.f, 0.f);
    for (int e = beg; e < end; e += 3) {
        int idx = e + grp;
        int cidx = min(idx, max(end - 1, 0));
        int u = g_col[cidx];
        float4 v = *(const float4*)(st + (size_t)u * 80 + 40 + sub * 4);
        if (active && idx < end) {
            acc.x += v.x; acc.y += v.y; acc.z += v.z; acc.w += v.w;
        }
    }
    // fold groups 1,2 into group 0 (read originals simultaneously)
    float4 gA, gB;
    gA.x = __shfl_down_sync(0xffffffffu, acc.x, 10);
    gA.y = __shfl_down_sync(0xffffffffu, acc.y, 10);
    gA.z = __shfl_down_sync(0xffffffffu, acc.z, 10);
    gA.w = __shfl_down_sync(0xffffffffu, acc.w, 10);
    gB.x = __shfl_down_sync(0xffffffffu, acc.x, 20);
    gB.y = __shfl_down_sync(0xffffffffu, acc.y, 20);
    gB.z = __shfl_down_sync(0xffffffffu, acc.z, 20);
    gB.w = __shfl_down_sync(0xffffffffu, acc.w, 20);

    if (lane < 10) {
        float inv = 1.0f / (float)max(end - beg, 1);
        float4 s = *(const float4*)(st + (size_t)w * 80 + sub * 4);
        float4 bb = *(const float4*)(b + sub * 4);
        float4 r;
        r.x = fmaf(acc.x + gA.x + gB.x, inv, s.x + bb.x);
        r.y = fmaf(acc.y + gA.y + gB.y, inv, s.y + bb.y);
        r.z = fmaf(acc.z + gA.z + gB.z, inv, s.z + bb.z);
        r.w = fmaf(acc.w + gA.w + gB.w, inv, s.w + bb.w);
        *(float4*)(out + (size_t)w * 40 + sub * 4) = r;
    }
}

// ---------------- launch ----------------
extern "C" void kernel_launch(void* const* d_in, const int* in_sizes, int n_in,
                              void* d_out, int out_size) {
    const float* x   = (const float*)d_in[0];
    const int*   src = (const int*)d_in[1];
    const int*   dst = (const int*)d_in[2];
    const float* ws1 = (const float*)d_in[3];
    const float* wn1 = (const float*)d_in[4];
    const float* b1  = (const float*)d_in[5];
    const float* ws2 = (const float*)d_in[6];
    const float* wn2 = (const float*)d_in[7];
    const float* b2  = (const float*)d_in[8];
    const float* ws3 = (const float*)d_in[9];
    const float* wn3 = (const float*)d_in[10];
    const float* b3  = (const float*)d_in[11];
    const float* ws4 = (const float*)d_in[12];
    const float* wn4 = (const float*)d_in[13];
    const float* b4  = (const float*)d_in[14];

    const int n = in_sizes[0] / 128;
    const int E = in_sizes[1];
    const int tiles = (n + 127) / 128;

    const int SMEM = 2 * 32768;
    cudaFuncSetAttribute(k_gemm_mma<4, false>, cudaFuncAttributeMaxDynamicSharedMemorySize, SMEM);
    cudaFuncSetAttribute(k_gemm_mma<2, true>,  cudaFuncAttributeMaxDynamicSharedMemorySize, SMEM);

    float* pst;
    uint4* pB;
    cudaGetSymbolAddress((void**)&pst, g_st);
    cudaGetSymbolAddress((void**)&pB, g_B);

    // preps (prep_x also zeroes deg)
    k_prep_x<<<(n * 32 + 255) / 256, 256>>>(x, n);
    k_prep_wall<<<dim3(16, 4), 256>>>(ws1, wn1, ws2, wn2, ws3, wn3, ws4, wn4);

    // CSR build (by dst)
    k_count<<<(E + 255) / 256, 256>>>(dst, E);
    int nb = (n + 511) / 512;
    k_scan1<<<nb, 512>>>(n);
    k_scan3b<<<nb, 512>>>(n, E, nb);
    k_scatter<<<(E + 255) / 256, 256>>>(src, dst, E);

    const int ga = (n + 7) / 8;

    // L1..L3: aggregate-then-GEMM (fused [Ws|Wn], relu)
    k_aggm<<<ga, 256>>>(n);
    k_gemm_mma<4, false><<<tiles, 256, SMEM>>>(pB + 0 * 4096, b1, nullptr, n);
    k_aggm<<<ga, 256>>>(n);
    k_gemm_mma<4, false><<<tiles, 256, SMEM>>>(pB + 1 * 4096, b2, nullptr, n);
    k_aggm<<<ga, 256>>>(n);
    k_gemm_mma<4, false><<<tiles, 256, SMEM>>>(pB + 2 * 4096, b3, nullptr, n);
    // L4: GEMM-then-gather (st = [Ws4;Wn4] h3, K=128), then final agg -> d_out
    k_gemm_mma<2, true><<<tiles, 256, SMEM>>>(pB + 3 * 4096, b4, pst, n);
    k_aggf<<<ga, 256>>>(pst, b4, (float*)d_out, n);
}

// round 8
// speedup vs baseline: 1.3866x; 1.3190x over previous
#include <cuda_runtime.h>
#include <cuda_fp16.h>

#define NN 100000
#define EE 1600000
#define TILES ((NN + 127) / 128)

// ---------------- scratch (static __device__, no allocation) ----------------
// Per tile: 4 fp16 planes (h:k0-63, h:k64-127, m:k0-63, m:k64-127).
// Plane = 128 rows x 128B (64 fp16, SW128-swizzled within row) = 16KB.
__device__ uint4 g_A[(size_t)TILES * 4 * 1024];   // ~51 MB
__device__ uint4 g_B[4 * 4 * 1024];               // per layer: 4 chunk planes, fp16
__device__ float g_s[(size_t)NN * 40];            // layer-4 self term, fp32
__device__ unsigned g_t[(size_t)NN * 24];         // layer-4 neigh term, fp16 (40 vals, pad 96B)
__device__ int   g_deg[NN];
__device__ int   g_rp[NN + 1];
__device__ int   g_cur[NN];
__device__ int   g_col[EE];
__device__ int   g_bsum[256];

// ---------------- helpers ----------------
__device__ __forceinline__ int swz(int x) { return x ^ ((x >> 3) & 0x70); }

__device__ __forceinline__ uint2 pack_h4(float4 v) {
    __half2 a = __floats2half2_rn(v.x, v.y);
    __half2 b = __floats2half2_rn(v.z, v.w);
    uint2 r;
    r.x = *(unsigned*)&a;
    r.y = *(unsigned*)&b;
    return r;
}

__device__ __forceinline__ unsigned smem_u32(const void* p) {
    unsigned a;
    asm("{ .reg .u64 t; cvta.to.shared.u64 t, %1; cvt.u32.u64 %0, t; }" : "=r"(a) : "l"(p));
    return a;
}
__device__ __forceinline__ void cp16(unsigned s, const void* g) {
    asm volatile("cp.async.cg.shared.global [%0], [%1], 16;" :: "r"(s), "l"(g));
}
__device__ __forceinline__ void cp_commit() { asm volatile("cp.async.commit_group;"); }
__device__ __forceinline__ void cp_wait0() { asm volatile("cp.async.wait_group 0;"); }
__device__ __forceinline__ void cp_wait1() { asm volatile("cp.async.wait_group 1;"); }

__device__ __forceinline__ void ldm_x4(unsigned* r, unsigned addr) {
    asm volatile("ldmatrix.sync.aligned.m8n8.x4.shared.b16 {%0,%1,%2,%3}, [%4];"
                 : "=r"(r[0]), "=r"(r[1]), "=r"(r[2]), "=r"(r[3]) : "r"(addr));
}
__device__ __forceinline__ void mma_f16(float* d, const unsigned* a, unsigned b0, unsigned b1) {
    asm volatile(
        "mma.sync.aligned.m16n8k16.row.col.f32.f16.f16.f32 "
        "{%0,%1,%2,%3}, {%4,%5,%6,%7}, {%8,%9}, {%0,%1,%2,%3};"
        : "+f"(d[0]), "+f"(d[1]), "+f"(d[2]), "+f"(d[3])
        : "r"(a[0]), "r"(a[1]), "r"(a[2]), "r"(a[3]), "r"(b0), "r"(b1));
}

// ---------------- prep: x -> fp16 planes (chunks 0,1); also zero deg ----------------
__global__ void k_prep_x(const float* __restrict__ x, int n) {
    int idx = blockIdx.x * 256 + threadIdx.x;
    if (idx < n) g_deg[idx] = 0;
    if (idx >= n * 32) return;
    int node = idx >> 5, k = (idx & 31) << 2;
    float4 v = *(const float4*)(x + (size_t)node * 128 + k);
    uint2 q = pack_h4(v);
    int tile = node >> 7, r = node & 127, chunk = k >> 6, kb = (k & 63) << 1;
    char* base = (char*)g_A + ((size_t)tile * 4 + chunk) * 16384;
    int off = ((r >> 3) << 10) + swz(((r & 7) << 7) + kb);
    *(uint2*)(base + off) = q;
}

// ---------------- prep: all weights -> fp16 planes; also count degrees ----------------
// blocks 0..63: weights (layer = bx>>4). blocks 64..: edge degree count.
__global__ void k_prep_wc(const float* __restrict__ ws1, const float* __restrict__ wn1,
                          const float* __restrict__ ws2, const float* __restrict__ wn2,
                          const float* __restrict__ ws3, const float* __restrict__ wn3,
                          const float* __restrict__ ws4, const float* __restrict__ wn4,
                          const int* __restrict__ dst, int E) {
    int bx = blockIdx.x;
    if (bx >= 64) {
        int i = (bx - 64) * 256 + threadIdx.x;
        if (i < E) atomicAdd(&g_deg[dst[i]], 1);
        return;
    }
    int layer = bx >> 4;
    int idx = (bx & 15) * 256 + threadIdx.x;   // 0..4095
    int f = idx >> 5, k = (idx & 31) << 2;
    int kb = (k & 63) << 1;
    int off = ((f >> 3) << 10) + swz(((f & 7) << 7) + kb);
    if (layer < 3) {
        const float* ws = (layer == 0) ? ws1 : (layer == 1) ? ws2 : ws3;
        const float* wn = (layer == 0) ? wn1 : (layer == 1) ? wn2 : wn3;
        float4 vs = *(const float4*)(ws + (size_t)f * 128 + k);
        float4 vn = *(const float4*)(wn + (size_t)f * 128 + k);
        int chunk = k >> 6;
        char* b0 = (char*)g_B + ((size_t)layer * 4 + chunk) * 16384;
        char* b1 = (char*)g_B + ((size_t)layer * 4 + chunk + 2) * 16384;
        *(uint2*)(b0 + off) = pack_h4(vs);
        *(uint2*)(b1 + off) = pack_h4(vn);
    } else {
        float4 v = make_float4(0.f, 0.f, 0.f, 0.f);
        if (f < 40) v = *(const float4*)(ws4 + (size_t)f * 128 + k);
        else if (f < 80) v = *(const float4*)(wn4 + (size_t)(f - 40) * 128 + k);
        int chunk = k >> 6;
        char* b0 = (char*)g_B + ((size_t)3 * 4 + chunk) * 16384;
        *(uint2*)(b0 + off) = pack_h4(v);
    }
}

// ---------------- CSR build ----------------
__global__ void k_scan1(int n) {
    __shared__ int s[512];
    int i = blockIdx.x * 512 + threadIdx.x;
    int v = (i < n) ? g_deg[i] : 0;
    s[threadIdx.x] = v;
    __syncthreads();
    for (int off = 1; off < 512; off <<= 1) {
        int t = (threadIdx.x >= off) ? s[threadIdx.x - off] : 0;
        __syncthreads();
        s[threadIdx.x] += t;
        __syncthreads();
    }
    if (i < n) g_rp[i] = s[threadIdx.x] - v;
    if (threadIdx.x == 511) g_bsum[blockIdx.x] = s[511];
}
__global__ void k_scan3b(int n, int e, int nb) {
    __shared__ int s[512];
    int tid = threadIdx.x, bid = blockIdx.x;
    s[tid] = (tid < nb && tid < bid) ? g_bsum[tid] : 0;
    __syncthreads();
    for (int off = 256; off >= 1; off >>= 1) {
        if (tid < off) s[tid] += s[tid + off];
        __syncthreads();
    }
    int offv = s[0];
    int i = bid * 512 + tid;
    if (i < n) {
        int r = g_rp[i] + offv;
        g_rp[i] = r;
        g_cur[i] = r;
    }
    if (i == 0) g_rp[n] = e;
}
__global__ void k_scatter(const int* __restrict__ src, const int* __restrict__ dst, int e) {
    int i = blockIdx.x * blockDim.x + threadIdx.x;
    if (i < e) {
        int d = dst[i];
        int p = atomicAdd(&g_cur[d], 1);
        g_col[p] = src[i];
    }
}

// ---------------- aggregation: m[v] = mean_in h[src] (fp16 planes -> m planes) ----------------
__global__ __launch_bounds__(256)
void k_aggm(int n) {
    int w = (blockIdx.x * 256 + threadIdx.x) >> 5;
    int lane = threadIdx.x & 31;
    if (w >= n) return;
    int beg = g_rp[w], end = g_rp[w + 1];

    const int chunk = lane >> 4, kb = (lane & 15) << 3;
    const char* Ab = (const char*)g_A;

    float4 acc = make_float4(0.f, 0.f, 0.f, 0.f);
    for (int e = beg; e < end; e += 4) {
        int i1 = min(e + 1, end - 1);
        int i2 = min(e + 2, end - 1);
        int i3 = min(e + 3, end - 1);
        int u0 = g_col[e], u1 = g_col[i1], u2 = g_col[i2], u3 = g_col[i3];
#define ROWADDR(u) (Ab + ((size_t)((u >> 7) * 4 + chunk)) * 16384 + \
                    (((u & 127) >> 3) << 10) + swz((((u & 127) & 7) << 7) + kb))
        uint2 q0 = *(const uint2*)ROWADDR(u0);
        uint2 q1 = *(const uint2*)ROWADDR(u1);
        uint2 q2 = *(const uint2*)ROWADDR(u2);
        uint2 q3 = *(const uint2*)ROWADDR(u3);
#undef ROWADDR
#define ACC4(q) do { \
        float2 f0 = __half22float2(*(__half2*)&(q).x); \
        float2 f1 = __half22float2(*(__half2*)&(q).y); \
        acc.x += f0.x; acc.y += f0.y; acc.z += f1.x; acc.w += f1.y; } while (0)
        ACC4(q0);
        if (e + 1 < end) ACC4(q1);
        if (e + 2 < end) ACC4(q2);
        if (e + 3 < end) ACC4(q3);
#undef ACC4
    }
    float inv = 1.0f / (float)max(end - beg, 1);
    acc.x *= inv; acc.y *= inv; acc.z *= inv; acc.w *= inv;

    int tile = w >> 7, r = w & 127;
    char* base = (char*)g_A + ((size_t)tile * 4 + 2 + chunk) * 16384;
    int off = ((r >> 3) << 10) + swz(((r & 7) << 7) + kb);
    *(uint2*)(base + off) = pack_h4(acc);
}

// ---------------- fp16 mma GEMM: D[128 x 128] = A[128 x 64*NC] * B[128 x 64*NC]^T ----------------
__device__ __forceinline__ void prefetch_chunk(char* smembase, int c, const uint4* gAt,
                                               const uint4* __restrict__ Bw, int tid) {
    char* buf = smembase + (c & 1) * 32768;
    const uint4* sa = gAt + (size_t)c * 1024;
    unsigned da = smem_u32(buf);
#pragma unroll
    for (int i = 0; i < 4; i++) cp16(da + (tid + i * 256) * 16, sa + tid + i * 256);
    const uint4* sb = Bw + (size_t)c * 1024;
    unsigned db = smem_u32(buf + 16384);
#pragma unroll
    for (int i = 0; i < 4; i++) cp16(db + (tid + i * 256) * 16, sb + tid + i * 256);
    cp_commit();
}

template <int NC, bool FINAL>
__global__ __launch_bounds__(256, 2)
void k_gemm_mma(const uint4* __restrict__ Bw, const float* __restrict__ bias, int n) {
    extern __shared__ char smem[];
    const int tid = threadIdx.x, wid = tid >> 5, lane = tid & 31;
    const int mh = wid >> 2, nq = wid & 3;
    const size_t tile = blockIdx.x;
    const unsigned sbase = smem_u32(smem);

    const uint4* gAt = g_A + tile * 4 * 1024;

    float acc[4][4][4];
#pragma unroll
    for (int a = 0; a < 4; a++)
#pragma unroll
        for (int b = 0; b < 4; b++)
#pragma unroll
            for (int c = 0; c < 4; c++) acc[a][b][c] = 0.f;

    const int arow = mh * 64 + (lane & 15);
    const int brow = nq * 32 + ((lane >> 4) << 3) + (lane & 7);

    prefetch_chunk(smem, 0, gAt, Bw, tid);

#pragma unroll 1
    for (int c = 0; c < NC; c++) {
        if (c < NC - 1) { prefetch_chunk(smem, c + 1, gAt, Bw, tid); cp_wait1(); }
        else cp_wait0();
        __syncthreads();

        unsigned bufu = sbase + (unsigned)((c & 1) * 32768);
        unsigned Ap = bufu, Bp = bufu + 16384u;
#pragma unroll
        for (int ks = 0; ks < 4; ks++) {
            unsigned afr[4][4];
            {
                int seg = ks * 2 + (lane >> 4);
                int inner = swz(((arow & 7) << 7) + seg * 16);
#pragma unroll
                for (int mt = 0; mt < 4; mt++)
                    ldm_x4(afr[mt], Ap + (unsigned)((((arow >> 3) + 2 * mt) << 10) + inner));
            }
            unsigned bfr[2][4];
            {
                int seg = ks * 2 + ((lane >> 3) & 1);
                int inner = swz(((brow & 7) << 7) + seg * 16);
#pragma unroll
                for (int nb = 0; nb < 2; nb++)
                    ldm_x4(bfr[nb], Bp + (unsigned)((((brow >> 3) + 2 * nb) << 10) + inner));
            }
#pragma unroll
            for (int mt = 0; mt < 4; mt++)
#pragma unroll
                for (int nt = 0; nt < 4; nt++)
                    mma_f16(acc[mt][nt], afr[mt],
                            bfr[nt >> 1][(nt & 1) * 2], bfr[nt >> 1][(nt & 1) * 2 + 1]);
        }
        __syncthreads();
    }

    // -------- epilogue --------
    const size_t base = tile * 128;
    const int rr = lane >> 2, cc = (lane & 3) * 2;

    if (FINAL) {
        float* stage = (float*)smem;   // stride 84 floats, cols 0..79
#pragma unroll
        for (int mt = 0; mt < 4; mt++)
#pragma unroll
            for (int nt = 0; nt < 4; nt++) {
                int col = nq * 32 + nt * 8 + cc;
                if (col < 80) {
                    int r = mh * 64 + mt * 16 + rr;
                    stage[r * 84 + col] = acc[mt][nt][0];
                    stage[r * 84 + col + 1] = acc[mt][nt][1];
                    stage[(r + 8) * 84 + col] = acc[mt][nt][2];
                    stage[(r + 8) * 84 + col + 1] = acc[mt][nt][3];
                }
            }
        __syncthreads();
        // s: cols 0..39 fp32
        for (int t = tid; t < 128 * 10; t += 256) {
            int nn = t / 10, c4 = t % 10;
            size_t gn = base + nn;
            if (gn < (size_t)n)
                *(float4*)(g_s + gn * 40 + c4 * 4) = *(float4*)(stage + nn * 84 + c4 * 4);
        }
        // t: cols 40..79 fp16 (20 half2 per node, padded row of 24)
        for (int t = tid; t < 128 * 20; t += 256) {
            int nn = t / 20, j = t % 20;
            size_t gn = base + nn;
            if (gn < (size_t)n) {
                __half2 h = __floats2half2_rn(stage[nn * 84 + 40 + 2 * j],
                                              stage[nn * 84 + 41 + 2 * j]);
                g_t[gn * 24 + j] = *(unsigned*)&h;
            }
        }
    } else {
        __half* stg = (__half*)smem;   // stride 132 halves
#pragma unroll
        for (int mt = 0; mt < 4; mt++)
#pragma unroll
            for (int nt = 0; nt < 4; nt++) {
                int r = mh * 64 + mt * 16 + rr;
                int col = nq * 32 + nt * 8 + cc;
                float bv0 = __ldg(bias + col), bv1 = __ldg(bias + col + 1);
                float v0 = fmaxf(acc[mt][nt][0] + bv0, 0.f);
                float v1 = fmaxf(acc[mt][nt][1] + bv1, 0.f);
                float v2 = fmaxf(acc[mt][nt][2] + bv0, 0.f);
                float v3 = fmaxf(acc[mt][nt][3] + bv1, 0.f);
                *(__half2*)(stg + r * 132 + col) = __floats2half2_rn(v0, v1);
                *(__half2*)(stg + (r + 8) * 132 + col) = __floats2half2_rn(v2, v3);
            }
        __syncthreads();
        for (int t = tid; t < 4096; t += 256) {
            int nn = t >> 5, g = t & 31;
            size_t gn = base + nn;
            if (gn < (size_t)n) {
                uint2 q = *(uint2*)(stg + nn * 132 + g * 4);
                int k0 = g * 4;
                int chunk = k0 >> 6, kb = (k0 & 63) << 1;
                char* bA = (char*)g_A + (tile * 4 + chunk) * 16384;
                int off = ((nn >> 3) << 10) + swz(((nn & 7) << 7) + kb);
                *(uint2*)(bA + off) = q;
            }
        }
    }
}

// ---------------- final aggregation: out[v] = s[v] + mean_t + b (fp16 gather) ----------------
__global__ __launch_bounds__(256)
void k_aggf(const float* __restrict__ b, float* __restrict__ out, int n) {
    int w = (blockIdx.x * 256 + threadIdx.x) >> 5;
    int lane = threadIdx.x & 31;
    if (w >= n) return;
    int beg = g_rp[w], end = g_rp[w + 1];

    const int l = min(lane, 19);
    float2 acc = make_float2(0.f, 0.f);
    for (int e = beg; e < end; e += 2) {
        int i1 = min(e + 1, end - 1);
        int u0 = g_col[e], u1 = g_col[i1];
        unsigned q0 = g_t[(size_t)u0 * 24 + l];
        unsigned q1 = g_t[(size_t)u1 * 24 + l];
        if (lane < 20) {
            float2 f0 = __half22float2(*(__half2*)&q0);
            acc.x += f0.x; acc.y += f0.y;
            if (e + 1 < end) {
                float2 f1 = __half22float2(*(__half2*)&q1);
                acc.x += f1.x; acc.y += f1.y;
            }
        }
    }
    if (lane < 20) {
        float inv = 1.0f / (float)max(end - beg, 1);
        float2 s = *(const float2*)(g_s + (size_t)w * 40 + 2 * lane);
        float2 bb = *(const float2*)(b + 2 * lane);
        float2 r;
        r.x = fmaf(acc.x, inv, s.x + bb.x);
        r.y = fmaf(acc.y, inv, s.y + bb.y);
        *(float2*)(out + (size_t)w * 40 + 2 * lane) = r;
    }
}

// ---------------- launch ----------------
extern "C" void kernel_launch(void* const* d_in, const int* in_sizes, int n_in,
                              void* d_out, int out_size) {
    const float* x   = (const float*)d_in[0];
    const int*   src = (const int*)d_in[1];
    const int*   dst = (const int*)d_in[2];
    const float* ws1 = (const float*)d_in[3];
    const float* wn1 = (const float*)d_in[4];
    const float* b1  = (const float*)d_in[5];
    const float* ws2 = (const float*)d_in[6];
    const float* wn2 = (const float*)d_in[7];
    const float* b2  = (const float*)d_in[8];
    const float* ws3 = (const float*)d_in[9];
    const float* wn3 = (const float*)d_in[10];
    const float* b3  = (const float*)d_in[11];
    const float* ws4 = (const float*)d_in[12];
    const float* wn4 = (const float*)d_in[13];
    const float* b4  = (const float*)d_in[14];

    const int n = in_sizes[0] / 128;
    const int E = in_sizes[1];
    const int tiles = (n + 127) / 128;

    const int SMEM = 2 * 32768;
    cudaFuncSetAttribute(k_gemm_mma<4, false>, cudaFuncAttributeMaxDynamicSharedMemorySize, SMEM);
    cudaFuncSetAttribute(k_gemm_mma<2, true>,  cudaFuncAttributeMaxDynamicSharedMemorySize, SMEM);

    uint4* pB;
    cudaGetSymbolAddress((void**)&pB, g_B);

    // preps (prep_x zeroes deg; prep_wc converts weights AND counts degrees)
    k_prep_x<<<(n * 32 + 255) / 256, 256>>>(x, n);
    k_prep_wc<<<64 + (E + 255) / 256, 256>>>(ws1, wn1, ws2, wn2, ws3, wn3, ws4, wn4, dst, E);

    // CSR build (by dst)
    int nb = (n + 511) / 512;
    k_scan1<<<nb, 512>>>(n);
    k_scan3b<<<nb, 512>>>(n, E, nb);
    k_scatter<<<(E + 255) / 256, 256>>>(src, dst, E);

    const int ga = (n + 7) / 8;

    // L1..L3: aggregate-then-GEMM (fused [Ws|Wn], relu)
    k_aggm<<<ga, 256>>>(n);
    k_gemm_mma<4, false><<<tiles, 256, SMEM>>>(pB + 0 * 4096, b1, n);
    k_aggm<<<ga, 256>>>(n);
    k_gemm_mma<4, false><<<tiles, 256, SMEM>>>(pB + 1 * 4096, b2, n);
    k_aggm<<<ga, 256>>>(n);
    k_gemm_mma<4, false><<<tiles, 256, SMEM>>>(pB + 2 * 4096, b3, n);
    // L4: GEMM-then-gather (s fp32, t fp16), then final agg -> d_out
    k_gemm_mma<2, true><<<tiles, 256, SMEM>>>(pB + 3 * 4096, b4, n);
    k_aggf<<<ga, 256>>>(b4, (float*)d_out, n);
}

// round 9
// speedup vs baseline: 1.3911x; 1.0032x over previous
#include <cuda_runtime.h>
#include <cuda_fp16.h>

#define NN 100000
#define EE 1600000
#define TILES ((NN + 127) / 128)

// ---------------- scratch (static __device__, no allocation) ----------------
// Per tile: 4 fp16 planes (h:k0-63, h:k64-127, m:k0-63, m:k64-127).
// Plane = 128 rows x 128B (64 fp16, SW128-swizzled within row) = 16KB.
__device__ uint4 g_A[(size_t)TILES * 4 * 1024];   // ~51 MB
__device__ uint4 g_B[4 * 4 * 1024];               // per layer: 4 chunk planes, fp16
__device__ float g_s[(size_t)NN * 40];            // layer-4 self term, fp32
__device__ unsigned g_t[(size_t)NN * 24];         // layer-4 neigh term, fp16 (40 vals, pad 96B)
__device__ int   g_deg[NN];
__device__ int   g_rp[NN + 1];
__device__ int   g_cur[NN];
__device__ int   g_col[EE];
__device__ int   g_bsum[256];

// ---------------- helpers ----------------
__device__ __forceinline__ int swz(int x) { return x ^ ((x >> 3) & 0x70); }

__device__ __forceinline__ uint2 pack_h4(float4 v) {
    __half2 a = __floats2half2_rn(v.x, v.y);
    __half2 b = __floats2half2_rn(v.z, v.w);
    uint2 r;
    r.x = *(unsigned*)&a;
    r.y = *(unsigned*)&b;
    return r;
}

__device__ __forceinline__ unsigned smem_u32(const void* p) {
    unsigned a;
    asm("{ .reg .u64 t; cvta.to.shared.u64 t, %1; cvt.u32.u64 %0, t; }" : "=r"(a) : "l"(p));
    return a;
}
__device__ __forceinline__ void cp16(unsigned s, const void* g) {
    asm volatile("cp.async.cg.shared.global [%0], [%1], 16;" :: "r"(s), "l"(g));
}
__device__ __forceinline__ void cp_commit() { asm volatile("cp.async.commit_group;"); }
__device__ __forceinline__ void cp_wait0() { asm volatile("cp.async.wait_group 0;"); }
__device__ __forceinline__ void cp_wait1() { asm volatile("cp.async.wait_group 1;"); }

__device__ __forceinline__ void ldm_x4(unsigned* r, unsigned addr) {
    asm volatile("ldmatrix.sync.aligned.m8n8.x4.shared.b16 {%0,%1,%2,%3}, [%4];"
                 : "=r"(r[0]), "=r"(r[1]), "=r"(r[2]), "=r"(r[3]) : "r"(addr));
}
__device__ __forceinline__ void mma_f16(float* d, const unsigned* a, unsigned b0, unsigned b1) {
    asm volatile(
        "mma.sync.aligned.m16n8k16.row.col.f32.f16.f16.f32 "
        "{%0,%1,%2,%3}, {%4,%5,%6,%7}, {%8,%9}, {%0,%1,%2,%3};"
        : "+f"(d[0]), "+f"(d[1]), "+f"(d[2]), "+f"(d[3])
        : "r"(a[0]), "r"(a[1]), "r"(a[2]), "r"(a[3]), "r"(b0), "r"(b1));
}

// ---------------- prep: x -> fp16 planes (chunks 0,1) + all weights ----------------
// blocks [0,64): weights (layer = bx>>4); blocks [64,..): x conversion.
__global__ void k_prep_all(const float* __restrict__ x,
                           const float* __restrict__ ws1, const float* __restrict__ wn1,
                           const float* __restrict__ ws2, const float* __restrict__ wn2,
                           const float* __restrict__ ws3, const float* __restrict__ wn3,
                           const float* __restrict__ ws4, const float* __restrict__ wn4,
                           int n) {
    int bx = blockIdx.x;
    if (bx < 64) {
        int layer = bx >> 4;
        int idx = (bx & 15) * 256 + threadIdx.x;   // 0..4095
        int f = idx >> 5, k = (idx & 31) << 2;
        int kb = (k & 63) << 1;
        int off = ((f >> 3) << 10) + swz(((f & 7) << 7) + kb);
        if (layer < 3) {
            const float* ws = (layer == 0) ? ws1 : (layer == 1) ? ws2 : ws3;
            const float* wn = (layer == 0) ? wn1 : (layer == 1) ? wn2 : wn3;
            float4 vs = *(const float4*)(ws + (size_t)f * 128 + k);
            float4 vn = *(const float4*)(wn + (size_t)f * 128 + k);
            int chunk = k >> 6;
            char* b0 = (char*)g_B + ((size_t)layer * 4 + chunk) * 16384;
            char* b1 = (char*)g_B + ((size_t)layer * 4 + chunk + 2) * 16384;
            *(uint2*)(b0 + off) = pack_h4(vs);
            *(uint2*)(b1 + off) = pack_h4(vn);
        } else {
            float4 v = make_float4(0.f, 0.f, 0.f, 0.f);
            if (f < 40) v = *(const float4*)(ws4 + (size_t)f * 128 + k);
            else if (f < 80) v = *(const float4*)(wn4 + (size_t)(f - 40) * 128 + k);
            int chunk = k >> 6;
            char* b0 = (char*)g_B + ((size_t)3 * 4 + chunk) * 16384;
            *(uint2*)(b0 + off) = pack_h4(v);
        }
        return;
    }
    int idx = (bx - 64) * 256 + threadIdx.x;
    if (idx >= n * 32) return;
    int node = idx >> 5, k = (idx & 31) << 2;
    float4 v = *(const float4*)(x + (size_t)node * 128 + k);
    uint2 q = pack_h4(v);
    int tile = node >> 7, r = node & 127, chunk = k >> 6, kb = (k & 63) << 1;
    char* base = (char*)g_A + ((size_t)tile * 4 + chunk) * 16384;
    int off = ((r >> 3) << 10) + swz(((r & 7) << 7) + kb);
    *(uint2*)(base + off) = q;
}

// ---------------- CSR build (side stream) ----------------
__global__ void k_zero_deg(int n) {
    int i = blockIdx.x * 256 + threadIdx.x;
    if (i < n) g_deg[i] = 0;
}
__global__ void k_count(const int* __restrict__ dst, int e) {
    int i = blockIdx.x * blockDim.x + threadIdx.x;
    if (i < e) atomicAdd(&g_deg[dst[i]], 1);
}
__global__ void k_scan1(int n) {
    __shared__ int s[512];
    int i = blockIdx.x * 512 + threadIdx.x;
    int v = (i < n) ? g_deg[i] : 0;
    s[threadIdx.x] = v;
    __syncthreads();
    for (int off = 1; off < 512; off <<= 1) {
        int t = (threadIdx.x >= off) ? s[threadIdx.x - off] : 0;
        __syncthreads();
        s[threadIdx.x] += t;
        __syncthreads();
    }
    if (i < n) g_rp[i] = s[threadIdx.x] - v;
    if (threadIdx.x == 511) g_bsum[blockIdx.x] = s[511];
}
__global__ void k_scan3b(int n, int e, int nb) {
    __shared__ int s[512];
    int tid = threadIdx.x, bid = blockIdx.x;
    s[tid] = (tid < nb && tid < bid) ? g_bsum[tid] : 0;
    __syncthreads();
    for (int off = 256; off >= 1; off >>= 1) {
        if (tid < off) s[tid] += s[tid + off];
        __syncthreads();
    }
    int offv = s[0];
    int i = bid * 512 + tid;
    if (i < n) {
        int r = g_rp[i] + offv;
        g_rp[i] = r;
        g_cur[i] = r;
    }
    if (i == 0) g_rp[n] = e;
}
__global__ void k_scatter(const int* __restrict__ src, const int* __restrict__ dst, int e) {
    int i = blockIdx.x * blockDim.x + threadIdx.x;
    if (i < e) {
        int d = dst[i];
        int p = atomicAdd(&g_cur[d], 1);
        g_col[p] = src[i];
    }
}

// ---------------- aggregation: m[v] = mean_in h[src] (fp16 planes -> m planes) ----------------
__global__ __launch_bounds__(256)
void k_aggm(int n) {
    int w = (blockIdx.x * 256 + threadIdx.x) >> 5;
    int lane = threadIdx.x & 31;
    if (w >= n) return;
    int beg = g_rp[w], end = g_rp[w + 1];

    const int chunk = lane >> 4, kb = (lane & 15) << 3;
    const char* Ab = (const char*)g_A;

    float4 acc = make_float4(0.f, 0.f, 0.f, 0.f);
    for (int e = beg; e < end; e += 4) {
        int i1 = min(e + 1, end - 1);
        int i2 = min(e + 2, end - 1);
        int i3 = min(e + 3, end - 1);
        int u0 = g_col[e], u1 = g_col[i1], u2 = g_col[i2], u3 = g_col[i3];
#define ROWADDR(u) (Ab + ((size_t)((u >> 7) * 4 + chunk)) * 16384 + \
                    (((u & 127) >> 3) << 10) + swz((((u & 127) & 7) << 7) + kb))
        uint2 q0 = *(const uint2*)ROWADDR(u0);
        uint2 q1 = *(const uint2*)ROWADDR(u1);
        uint2 q2 = *(const uint2*)ROWADDR(u2);
        uint2 q3 = *(const uint2*)ROWADDR(u3);
#undef ROWADDR
#define ACC4(q) do { \
        float2 f0 = __half22float2(*(__half2*)&(q).x); \
        float2 f1 = __half22float2(*(__half2*)&(q).y); \
        acc.x += f0.x; acc.y += f0.y; acc.z += f1.x; acc.w += f1.y; } while (0)
        ACC4(q0);
        if (e + 1 < end) ACC4(q1);
        if (e + 2 < end) ACC4(q2);
        if (e + 3 < end) ACC4(q3);
#undef ACC4
    }
    float inv = 1.0f / (float)max(end - beg, 1);
    acc.x *= inv; acc.y *= inv; acc.z *= inv; acc.w *= inv;

    int tile = w >> 7, r = w & 127;
    char* base = (char*)g_A + ((size_t)tile * 4 + 2 + chunk) * 16384;
    int off = ((r >> 3) << 10) + swz(((r & 7) << 7) + kb);
    *(uint2*)(base + off) = pack_h4(acc);
}

// ---------------- fp16 mma GEMM: D[128 x 128] = A[128 x 64*NC] * B[128 x 64*NC]^T ----------------
__device__ __forceinline__ void prefetch_chunk(char* smembase, int c, const uint4* gAt,
                                               const uint4* __restrict__ Bw, int tid) {
    char* buf = smembase + (c & 1) * 32768;
    const uint4* sa = gAt + (size_t)c * 1024;
    unsigned da = smem_u32(buf);
#pragma unroll
    for (int i = 0; i < 4; i++) cp16(da + (tid + i * 256) * 16, sa + tid + i * 256);
    const uint4* sb = Bw + (size_t)c * 1024;
    unsigned db = smem_u32(buf + 16384);
#pragma unroll
    for (int i = 0; i < 4; i++) cp16(db + (tid + i * 256) * 16, sb + tid + i * 256);
    cp_commit();
}

template <int NC, bool FINAL>
__global__ __launch_bounds__(256, 2)
void k_gemm_mma(const uint4* __restrict__ Bw, const float* __restrict__ bias, int n) {
    extern __shared__ char smem[];
    const int tid = threadIdx.x, wid = tid >> 5, lane = tid & 31;
    const int mh = wid >> 2, nq = wid & 3;
    const size_t tile = blockIdx.x;
    const unsigned sbase = smem_u32(smem);

    const uint4* gAt = g_A + tile * 4 * 1024;

    float acc[4][4][4];
#pragma unroll
    for (int a = 0; a < 4; a++)
#pragma unroll
        for (int b = 0; b < 4; b++)
#pragma unroll
            for (int c = 0; c < 4; c++) acc[a][b][c] = 0.f;

    const int arow = mh * 64 + (lane & 15);
    const int brow = nq * 32 + ((lane >> 4) << 3) + (lane & 7);

    prefetch_chunk(smem, 0, gAt, Bw, tid);

#pragma unroll 1
    for (int c = 0; c < NC; c++) {
        if (c < NC - 1) { prefetch_chunk(smem, c + 1, gAt, Bw, tid); cp_wait1(); }
        else cp_wait0();
        __syncthreads();

        unsigned bufu = sbase + (unsigned)((c & 1) * 32768);
        unsigned Ap = bufu, Bp = bufu + 16384u;
#pragma unroll
        for (int ks = 0; ks < 4; ks++) {
            unsigned afr[4][4];
            {
                int seg = ks * 2 + (lane >> 4);
                int inner = swz(((arow & 7) << 7) + seg * 16);
#pragma unroll
                for (int mt = 0; mt < 4; mt++)
                    ldm_x4(afr[mt], Ap + (unsigned)((((arow >> 3) + 2 * mt) << 10) + inner));
            }
            unsigned bfr[2][4];
            {
                int seg = ks * 2 + ((lane >> 3) & 1);
                int inner = swz(((brow & 7) << 7) + seg * 16);
#pragma unroll
                for (int nb = 0; nb < 2; nb++)
                    ldm_x4(bfr[nb], Bp + (unsigned)((((brow >> 3) + 2 * nb) << 10) + inner));
            }
#pragma unroll
            for (int mt = 0; mt < 4; mt++)
#pragma unroll
                for (int nt = 0; nt < 4; nt++)
                    mma_f16(acc[mt][nt], afr[mt],
                            bfr[nt >> 1][(nt & 1) * 2], bfr[nt >> 1][(nt & 1) * 2 + 1]);
        }
        __syncthreads();
    }

    // -------- epilogue --------
    const size_t base = tile * 128;
    const int rr = lane >> 2, cc = (lane & 3) * 2;

    if (FINAL) {
        float* stage = (float*)smem;   // stride 84 floats, cols 0..79
#pragma unroll
        for (int mt = 0; mt < 4; mt++)
#pragma unroll
            for (int nt = 0; nt < 4; nt++) {
                int col = nq * 32 + nt * 8 + cc;
                if (col < 80) {
                    int r = mh * 64 + mt * 16 + rr;
                    stage[r * 84 + col] = acc[mt][nt][0];
                    stage[r * 84 + col + 1] = acc[mt][nt][1];
                    stage[(r + 8) * 84 + col] = acc[mt][nt][2];
                    stage[(r + 8) * 84 + col + 1] = acc[mt][nt][3];
                }
            }
        __syncthreads();
        // s: cols 0..39 fp32
        for (int t = tid; t < 128 * 10; t += 256) {
            int nn = t / 10, c4 = t % 10;
            size_t gn = base + nn;
            if (gn < (size_t)n)
                *(float4*)(g_s + gn * 40 + c4 * 4) = *(float4*)(stage + nn * 84 + c4 * 4);
        }
        // t: cols 40..79 fp16 (20 half2 per node, padded row of 24)
        for (int t = tid; t < 128 * 20; t += 256) {
            int nn = t / 20, j = t % 20;
            size_t gn = base + nn;
            if (gn < (size_t)n) {
                __half2 h = __floats2half2_rn(stage[nn * 84 + 40 + 2 * j],
                                              stage[nn * 84 + 41 + 2 * j]);
                g_t[gn * 24 + j] = *(unsigned*)&h;
            }
        }
    } else {
        __half* stg = (__half*)smem;   // stride 132 halves
#pragma unroll
        for (int mt = 0; mt < 4; mt++)
#pragma unroll
            for (int nt = 0; nt < 4; nt++) {
                int r = mh * 64 + mt * 16 + rr;
                int col = nq * 32 + nt * 8 + cc;
                float bv0 = __ldg(bias + col), bv1 = __ldg(bias + col + 1);
                float v0 = fmaxf(acc[mt][nt][0] + bv0, 0.f);
                float v1 = fmaxf(acc[mt][nt][1] + bv1, 0.f);
                float v2 = fmaxf(acc[mt][nt][2] + bv0, 0.f);
                float v3 = fmaxf(acc[mt][nt][3] + bv1, 0.f);
                *(__half2*)(stg + r * 132 + col) = __floats2half2_rn(v0, v1);
                *(__half2*)(stg + (r + 8) * 132 + col) = __floats2half2_rn(v2, v3);
            }
        __syncthreads();
        for (int t = tid; t < 4096; t += 256) {
            int nn = t >> 5, g = t & 31;
            size_t gn = base + nn;
            if (gn < (size_t)n) {
                uint2 q = *(uint2*)(stg + nn * 132 + g * 4);
                int k0 = g * 4;
                int chunk = k0 >> 6, kb = (k0 & 63) << 1;
                char* bA = (char*)g_A + (tile * 4 + chunk) * 16384;
                int off = ((nn >> 3) << 10) + swz(((nn & 7) << 7) + kb);
                *(uint2*)(bA + off) = q;
            }
        }
    }
}

// ---------------- final aggregation: out[v] = s[v] + mean_t + b (fp16 gather) ----------------
__global__ __launch_bounds__(256)
void k_aggf(const float* __restrict__ b, float* __restrict__ out, int n) {
    int w = (blockIdx.x * 256 + threadIdx.x) >> 5;
    int lane = threadIdx.x & 31;
    if (w >= n) return;
    int beg = g_rp[w], end = g_rp[w + 1];

    const int l = min(lane, 19);
    float2 acc = make_float2(0.f, 0.f);
    for (int e = beg; e < end; e += 2) {
        int i1 = min(e + 1, end - 1);
        int u0 = g_col[e], u1 = g_col[i1];
        unsigned q0 = g_t[(size_t)u0 * 24 + l];
        unsigned q1 = g_t[(size_t)u1 * 24 + l];
        if (lane < 20) {
            float2 f0 = __half22float2(*(__half2*)&q0);
            acc.x += f0.x; acc.y += f0.y;
            if (e + 1 < end) {
                float2 f1 = __half22float2(*(__half2*)&q1);
                acc.x += f1.x; acc.y += f1.y;
            }
        }
    }
    if (lane < 20) {
        float inv = 1.0f / (float)max(end - beg, 1);
        float2 s = *(const float2*)(g_s + (size_t)w * 40 + 2 * lane);
        float2 bb = *(const float2*)(b + 2 * lane);
        float2 r;
        r.x = fmaf(acc.x, inv, s.x + bb.x);
        r.y = fmaf(acc.y, inv, s.y + bb.y);
        *(float2*)(out + (size_t)w * 40 + 2 * lane) = r;
    }
}

// ---------------- launch ----------------
extern "C" void kernel_launch(void* const* d_in, const int* in_sizes, int n_in,
                              void* d_out, int out_size) {
    const float* x   = (const float*)d_in[0];
    const int*   src = (const int*)d_in[1];
    const int*   dst = (const int*)d_in[2];
    const float* ws1 = (const float*)d_in[3];
    const float* wn1 = (const float*)d_in[4];
    const float* b1  = (const float*)d_in[5];
    const float* ws2 = (const float*)d_in[6];
    const float* wn2 = (const float*)d_in[7];
    const float* b2  = (const float*)d_in[8];
    const float* ws3 = (const float*)d_in[9];
    const float* wn3 = (const float*)d_in[10];
    const float* b3  = (const float*)d_in[11];
    const float* ws4 = (const float*)d_in[12];
    const float* wn4 = (const float*)d_in[13];
    const float* b4  = (const float*)d_in[14];

    const int n = in_sizes[0] / 128;
    const int E = in_sizes[1];
    const int tiles = (n + 127) / 128;

    const int SMEM = 2 * 32768;
    cudaFuncSetAttribute(k_gemm_mma<4, false>, cudaFuncAttributeMaxDynamicSharedMemorySize, SMEM);
    cudaFuncSetAttribute(k_gemm_mma<2, true>,  cudaFuncAttributeMaxDynamicSharedMemorySize, SMEM);

    uint4* pB;
    cudaGetSymbolAddress((void**)&pB, g_B);

    // fork: CSR chain on a non-blocking side stream, overlapped with preps.
    // (host-side creates run only on the correctness + capture calls; the
    //  captured graph contains only the GPU ops + dependencies)
    cudaStream_t s2;
    cudaStreamCreateWithFlags(&s2, cudaStreamNonBlocking);
    cudaEvent_t evFork, evJoin;
    cudaEventCreateWithFlags(&evFork, cudaEventDisableTiming);
    cudaEventCreateWithFlags(&evJoin, cudaEventDisableTiming);

    cudaEventRecord(evFork, 0);
    cudaStreamWaitEvent(s2, evFork, 0);

    // side stream: CSR build (by dst)
    k_zero_deg<<<(n + 255) / 256, 256, 0, s2>>>(n);
    k_count<<<(E + 255) / 256, 256, 0, s2>>>(dst, E);
    int nb = (n + 511) / 512;
    k_scan1<<<nb, 512, 0, s2>>>(n);
    k_scan3b<<<nb, 512, 0, s2>>>(n, E, nb);
    k_scatter<<<(E + 255) / 256, 256, 0, s2>>>(src, dst, E);
    cudaEventRecord(evJoin, s2);

    // main stream: x + weight conversion
    k_prep_all<<<64 + (n * 32 + 255) / 256, 256>>>(x, ws1, wn1, ws2, wn2,
                                                   ws3, wn3, ws4, wn4, n);

    // join: layers need both CSR and planes
    cudaStreamWaitEvent(0, evJoin, 0);

    const int ga = (n + 7) / 8;

    // L1..L3: aggregate-then-GEMM (fused [Ws|Wn], relu)
    k_aggm<<<ga, 256>>>(n);
    k_gemm_mma<4, false><<<tiles, 256, SMEM>>>(pB + 0 * 4096, b1, n);
    k_aggm<<<ga, 256>>>(n);
    k_gemm_mma<4, false><<<tiles, 256, SMEM>>>(pB + 1 * 4096, b2, n);
    k_aggm<<<ga, 256>>>(n);
    k_gemm_mma<4, false><<<tiles, 256, SMEM>>>(pB + 2 * 4096, b3, n);
    // L4: GEMM-then-gather (s fp32, t fp16), then final agg -> d_out
    k_gemm_mma<2, true><<<tiles, 256, SMEM>>>(pB + 3 * 4096, b4, n);
    k_aggf<<<ga, 256>>>(b4, (float*)d_out, n);

    // cleanup of host-side handles (safe: events already consumed by graph deps)
    cudaEventDestroy(evFork);
    cudaEventDestroy(evJoin);
    cudaStreamDestroy(s2);
}

// round 10
// speedup vs baseline: 1.4422x; 1.0368x over previous
#include <cuda_runtime.h>
#include <cuda_fp16.h>

#define NN 100000
#define EE 1600000
#define TILES ((NN + 127) / 128)

// ---------------- scratch (static __device__, no allocation) ----------------
__device__ uint4 g_A[(size_t)TILES * 4 * 1024];   // per tile: h k0,h k64,m k0,m k64 planes
__device__ uint4 g_B[4 * 4 * 1024];               // per layer: 4 chunk planes, fp16
__device__ float g_s[(size_t)NN * 40];            // layer-4 self term, fp32
__device__ unsigned g_t[(size_t)NN * 24];         // layer-4 neigh term, fp16 (40 vals, pad 96B)
__device__ int   g_deg[NN];
__device__ int   g_rp[NN + 1];
__device__ int   g_cur[NN];
__device__ int   g_col[EE];
__device__ int   g_bsum[256];

// ---------------- helpers ----------------
__device__ __forceinline__ int swz(int x) { return x ^ ((x >> 3) & 0x70); }

__device__ __forceinline__ uint2 pack_h4(float4 v) {
    __half2 a = __floats2half2_rn(v.x, v.y);
    __half2 b = __floats2half2_rn(v.z, v.w);
    uint2 r;
    r.x = *(unsigned*)&a;
    r.y = *(unsigned*)&b;
    return r;
}

__device__ __forceinline__ unsigned smem_u32(const void* p) {
    unsigned a;
    asm("{ .reg .u64 t; cvta.to.shared.u64 t, %1; cvt.u32.u64 %0, t; }" : "=r"(a) : "l"(p));
    return a;
}
__device__ __forceinline__ void cp16(unsigned s, const void* g) {
    asm volatile("cp.async.cg.shared.global [%0], [%1], 16;" :: "r"(s), "l"(g));
}
__device__ __forceinline__ void cp_commit() { asm volatile("cp.async.commit_group;"); }
__device__ __forceinline__ void cp_wait0() { asm volatile("cp.async.wait_group 0;"); }
__device__ __forceinline__ void cp_wait1() { asm volatile("cp.async.wait_group 1;"); }

__device__ __forceinline__ void grid_wait() {
    asm volatile("griddepcontrol.wait;" ::: "memory");
}
__device__ __forceinline__ void grid_trigger() {
    asm volatile("griddepcontrol.launch_dependents;");
}

__device__ __forceinline__ void ldm_x4(unsigned* r, unsigned addr) {
    asm volatile("ldmatrix.sync.aligned.m8n8.x4.shared.b16 {%0,%1,%2,%3}, [%4];"
                 : "=r"(r[0]), "=r"(r[1]), "=r"(r[2]), "=r"(r[3]) : "r"(addr));
}
__device__ __forceinline__ void mma_f16(float* d, const unsigned* a, unsigned b0, unsigned b1) {
    asm volatile(
        "mma.sync.aligned.m16n8k16.row.col.f32.f16.f16.f32 "
        "{%0,%1,%2,%3}, {%4,%5,%6,%7}, {%8,%9}, {%0,%1,%2,%3};"
        : "+f"(d[0]), "+f"(d[1]), "+f"(d[2]), "+f"(d[3])
        : "r"(a[0]), "r"(a[1]), "r"(a[2]), "r"(a[3]), "r"(b0), "r"(b1));
}

__device__ __forceinline__ void mma_chunk(float acc[4][4][4], unsigned Ap, unsigned Bp,
                                          int arow, int brow, int lane) {
#pragma unroll
    for (int ks = 0; ks < 4; ks++) {
        unsigned afr[4][4];
        {
            int seg = ks * 2 + (lane >> 4);
            int inner = swz(((arow & 7) << 7) + seg * 16);
#pragma unroll
            for (int mt = 0; mt < 4; mt++)
                ldm_x4(afr[mt], Ap + (unsigned)((((arow >> 3) + 2 * mt) << 10) + inner));
        }
        unsigned bfr[2][4];
        {
            int seg = ks * 2 + ((lane >> 3) & 1);
            int inner = swz(((brow & 7) << 7) + seg * 16);
#pragma unroll
            for (int nb = 0; nb < 2; nb++)
                ldm_x4(bfr[nb], Bp + (unsigned)((((brow >> 3) + 2 * nb) << 10) + inner));
        }
#pragma unroll
        for (int mt = 0; mt < 4; mt++)
#pragma unroll
            for (int nt = 0; nt < 4; nt++)
                mma_f16(acc[mt][nt], afr[mt],
                        bfr[nt >> 1][(nt & 1) * 2], bfr[nt >> 1][(nt & 1) * 2 + 1]);
    }
}

// ---------------- prep: x -> fp16 planes (chunks 0,1) + all weights ----------------
__global__ void k_prep_all(const float* __restrict__ x,
                           const float* __restrict__ ws1, const float* __restrict__ wn1,
                           const float* __restrict__ ws2, const float* __restrict__ wn2,
                           const float* __restrict__ ws3, const float* __restrict__ wn3,
                           const float* __restrict__ ws4, const float* __restrict__ wn4,
                           int n) {
    int bx = blockIdx.x;
    if (bx < 64) {
        int layer = bx >> 4;
        int idx = (bx & 15) * 256 + threadIdx.x;   // 0..4095
        int f = idx >> 5, k = (idx & 31) << 2;
        int kb = (k & 63) << 1;
        int off = ((f >> 3) << 10) + swz(((f & 7) << 7) + kb);
        if (layer < 3) {
            const float* ws = (layer == 0) ? ws1 : (layer == 1) ? ws2 : ws3;
            const float* wn = (layer == 0) ? wn1 : (layer == 1) ? wn2 : wn3;
            float4 vs = *(const float4*)(ws + (size_t)f * 128 + k);
            float4 vn = *(const float4*)(wn + (size_t)f * 128 + k);
            int chunk = k >> 6;
            char* b0 = (char*)g_B + ((size_t)layer * 4 + chunk) * 16384;
            char* b1 = (char*)g_B + ((size_t)layer * 4 + chunk + 2) * 16384;
            *(uint2*)(b0 + off) = pack_h4(vs);
            *(uint2*)(b1 + off) = pack_h4(vn);
        } else {
            float4 v = make_float4(0.f, 0.f, 0.f, 0.f);
            if (f < 40) v = *(const float4*)(ws4 + (size_t)f * 128 + k);
            else if (f < 80) v = *(const float4*)(wn4 + (size_t)(f - 40) * 128 + k);
            int chunk = k >> 6;
            char* b0 = (char*)g_B + ((size_t)3 * 4 + chunk) * 16384;
            *(uint2*)(b0 + off) = pack_h4(v);
        }
        return;
    }
    int idx = (bx - 64) * 256 + threadIdx.x;
    if (idx >= n * 32) return;
    int node = idx >> 5, k = (idx & 31) << 2;
    float4 v = *(const float4*)(x + (size_t)node * 128 + k);
    uint2 q = pack_h4(v);
    int tile = node >> 7, r = node & 127, chunk = k >> 6, kb = (k & 63) << 1;
    char* base = (char*)g_A + ((size_t)tile * 4 + chunk) * 16384;
    int off = ((r >> 3) << 10) + swz(((r & 7) << 7) + kb);
    *(uint2*)(base + off) = q;
}

// ---------------- CSR build (side stream) ----------------
__global__ void k_zero_deg(int n) {
    int i = blockIdx.x * 256 + threadIdx.x;
    if (i < n) g_deg[i] = 0;
}
__global__ void k_count(const int* __restrict__ dst, int e) {
    int i = blockIdx.x * blockDim.x + threadIdx.x;
    if (i < e) atomicAdd(&g_deg[dst[i]], 1);
}
__global__ void k_scan1(int n) {
    __shared__ int s[512];
    int i = blockIdx.x * 512 + threadIdx.x;
    int v = (i < n) ? g_deg[i] : 0;
    s[threadIdx.x] = v;
    __syncthreads();
    for (int off = 1; off < 512; off <<= 1) {
        int t = (threadIdx.x >= off) ? s[threadIdx.x - off] : 0;
        __syncthreads();
        s[threadIdx.x] += t;
        __syncthreads();
    }
    if (i < n) g_rp[i] = s[threadIdx.x] - v;
    if (threadIdx.x == 511) g_bsum[blockIdx.x] = s[511];
}
__global__ void k_scan3b(int n, int e, int nb) {
    __shared__ int s[512];
    int tid = threadIdx.x, bid = blockIdx.x;
    s[tid] = (tid < nb && tid < bid) ? g_bsum[tid] : 0;
    __syncthreads();
    for (int off = 256; off >= 1; off >>= 1) {
        if (tid < off) s[tid] += s[tid + off];
        __syncthreads();
    }
    int offv = s[0];
    int i = bid * 512 + tid;
    if (i < n) {
        int r = g_rp[i] + offv;
        g_rp[i] = r;
        g_cur[i] = r;
    }
    if (i == 0) g_rp[n] = e;
}
__global__ void k_scatter(const int* __restrict__ src, const int* __restrict__ dst, int e) {
    int i = blockIdx.x * blockDim.x + threadIdx.x;
    if (i < e) {
        int d = dst[i];
        int p = atomicAdd(&g_cur[d], 1);
        g_col[p] = src[i];
    }
}

// ---------------- aggregation: m[v] = mean_in h[src] (fp16 planes -> m planes) ----------------
// Triggers dependent gemm launch at entry (all blocks started => gemm can begin
// its h-chunk phase while aggregation finishes; gemm grid_wait()s before m use).
__global__ __launch_bounds__(256)
void k_aggm(int n) {
    if (threadIdx.x == 0) grid_trigger();
    int w = (blockIdx.x * 256 + threadIdx.x) >> 5;
    int lane = threadIdx.x & 31;
    if (w >= n) return;
    int beg = g_rp[w], end = g_rp[w + 1];

    const int chunk = lane >> 4, kb = (lane & 15) << 3;
    const char* Ab = (const char*)g_A;

    float4 acc = make_float4(0.f, 0.f, 0.f, 0.f);
    for (int e = beg; e < end; e += 4) {
        int i1 = min(e + 1, end - 1);
        int i2 = min(e + 2, end - 1);
        int i3 = min(e + 3, end - 1);
        int u0 = g_col[e], u1 = g_col[i1], u2 = g_col[i2], u3 = g_col[i3];
#define ROWADDR(u) (Ab + ((size_t)((u >> 7) * 4 + chunk)) * 16384 + \
                    (((u & 127) >> 3) << 10) + swz((((u & 127) & 7) << 7) + kb))
        uint2 q0 = *(const uint2*)ROWADDR(u0);
        uint2 q1 = *(const uint2*)ROWADDR(u1);
        uint2 q2 = *(const uint2*)ROWADDR(u2);
        uint2 q3 = *(const uint2*)ROWADDR(u3);
#undef ROWADDR
#define ACC4(q) do { \
        float2 f0 = __half22float2(*(__half2*)&(q).x); \
        float2 f1 = __half22float2(*(__half2*)&(q).y); \
        acc.x += f0.x; acc.y += f0.y; acc.z += f1.x; acc.w += f1.y; } while (0)
        ACC4(q0);
        if (e + 1 < end) ACC4(q1);
        if (e + 2 < end) ACC4(q2);
        if (e + 3 < end) ACC4(q3);
#undef ACC4
    }
    float inv = 1.0f / (float)max(end - beg, 1);
    acc.x *= inv; acc.y *= inv; acc.z *= inv; acc.w *= inv;

    int tile = w >> 7, r = w & 127;
    char* base = (char*)g_A + ((size_t)tile * 4 + 2 + chunk) * 16384;
    int off = ((r >> 3) << 10) + swz(((r & 7) << 7) + kb);
    *(uint2*)(base + off) = pack_h4(acc);
}

// ---------------- GEMM pieces ----------------
__device__ __forceinline__ void prefetch_chunk(char* smembase, int c, const uint4* gAt,
                                               const uint4* __restrict__ Bw, int tid) {
    char* buf = smembase + (c & 1) * 32768;
    const uint4* sa = gAt + (size_t)c * 1024;
    unsigned da = smem_u32(buf);
#pragma unroll
    for (int i = 0; i < 4; i++) cp16(da + (tid + i * 256) * 16, sa + tid + i * 256);
    const uint4* sb = Bw + (size_t)c * 1024;
    unsigned db = smem_u32(buf + 16384);
#pragma unroll
    for (int i = 0; i < 4; i++) cp16(db + (tid + i * 256) * 16, sb + tid + i * 256);
    cp_commit();
}

// hidden layers: PDL-split. Chunks 0,1 (h x Ws) run before grid_wait; chunks
// 2,3 (m x Wn) after. Writes next h planes (fp16, swizzled) in epilogue.
__global__ __launch_bounds__(256, 2)
void k_gemm_hid(const uint4* __restrict__ Bw, const float* __restrict__ bias, int n) {
    extern __shared__ char smem[];
    const int tid = threadIdx.x, wid = tid >> 5, lane = tid & 31;
    const int mh = wid >> 2, nq = wid & 3;
    const size_t tile = blockIdx.x;
    const unsigned sbase = smem_u32(smem);
    const uint4* gAt = g_A + tile * 4 * 1024;

    float acc[4][4][4];
#pragma unroll
    for (int a = 0; a < 4; a++)
#pragma unroll
        for (int b = 0; b < 4; b++)
#pragma unroll
            for (int c = 0; c < 4; c++) acc[a][b][c] = 0.f;

    const int arow = mh * 64 + (lane & 15);
    const int brow = nq * 32 + ((lane >> 4) << 3) + (lane & 7);

    // phase 1: h chunks (independent of the producing aggm)
    prefetch_chunk(smem, 0, gAt, Bw, tid);
    prefetch_chunk(smem, 1, gAt, Bw, tid);
    cp_wait1();
    __syncthreads();
    mma_chunk(acc, sbase, sbase + 16384u, arow, brow, lane);
    cp_wait0();
    __syncthreads();
    mma_chunk(acc, sbase + 32768u, sbase + 49152u, arow, brow, lane);

    // phase 2: m chunks (require aggm grid completion)
    grid_wait();
    __syncthreads();
    prefetch_chunk(smem, 2, gAt, Bw, tid);
    prefetch_chunk(smem, 3, gAt, Bw, tid);
    cp_wait1();
    __syncthreads();
    mma_chunk(acc, sbase, sbase + 16384u, arow, brow, lane);
    cp_wait0();
    __syncthreads();
    mma_chunk(acc, sbase + 32768u, sbase + 49152u, arow, brow, lane);
    __syncthreads();

    // epilogue
    const size_t base = tile * 128;
    const int rr = lane >> 2, cc = (lane & 3) * 2;
    __half* stg = (__half*)smem;   // stride 132 halves
#pragma unroll
    for (int mt = 0; mt < 4; mt++)
#pragma unroll
        for (int nt = 0; nt < 4; nt++) {
            int r = mh * 64 + mt * 16 + rr;
            int col = nq * 32 + nt * 8 + cc;
            float bv0 = __ldg(bias + col), bv1 = __ldg(bias + col + 1);
            float v0 = fmaxf(acc[mt][nt][0] + bv0, 0.f);
            float v1 = fmaxf(acc[mt][nt][1] + bv1, 0.f);
            float v2 = fmaxf(acc[mt][nt][2] + bv0, 0.f);
            float v3 = fmaxf(acc[mt][nt][3] + bv1, 0.f);
            *(__half2*)(stg + r * 132 + col) = __floats2half2_rn(v0, v1);
            *(__half2*)(stg + (r + 8) * 132 + col) = __floats2half2_rn(v2, v3);
        }
    __syncthreads();
    for (int t = tid; t < 4096; t += 256) {
        int nn = t >> 5, g = t & 31;
        size_t gn = base + nn;
        if (gn < (size_t)n) {
            uint2 q = *(uint2*)(stg + nn * 132 + g * 4);
            int k0 = g * 4;
            int chunk = k0 >> 6, kb = (k0 & 63) << 1;
            char* bA = (char*)g_A + (tile * 4 + chunk) * 16384;
            int off = ((nn >> 3) << 10) + swz(((nn & 7) << 7) + kb);
            *(uint2*)(bA + off) = q;
        }
    }
}

// final layer: st = [Ws4;Wn4] h3 over K=128 (chunks 0,1). Entry wait.
__global__ __launch_bounds__(256, 2)
void k_gemm_fin(const uint4* __restrict__ Bw, const float* __restrict__ bias, int n) {
    grid_wait();
    extern __shared__ char smem[];
    const int tid = threadIdx.x, wid = tid >> 5, lane = tid & 31;
    const int mh = wid >> 2, nq = wid & 3;
    const size_t tile = blockIdx.x;
    const unsigned sbase = smem_u32(smem);
    const uint4* gAt = g_A + tile * 4 * 1024;

    float acc[4][4][4];
#pragma unroll
    for (int a = 0; a < 4; a++)
#pragma unroll
        for (int b = 0; b < 4; b++)
#pragma unroll
            for (int c = 0; c < 4; c++) acc[a][b][c] = 0.f;

    const int arow = mh * 64 + (lane & 15);
    const int brow = nq * 32 + ((lane >> 4) << 3) + (lane & 7);

    prefetch_chunk(smem, 0, gAt, Bw, tid);
    prefetch_chunk(smem, 1, gAt, Bw, tid);
    cp_wait1();
    __syncthreads();
    mma_chunk(acc, sbase, sbase + 16384u, arow, brow, lane);
    cp_wait0();
    __syncthreads();
    mma_chunk(acc, sbase + 32768u, sbase + 49152u, arow, brow, lane);
    __syncthreads();

    const size_t base = tile * 128;
    const int rr = lane >> 2, cc = (lane & 3) * 2;
    float* stage = (float*)smem;   // stride 84 floats, cols 0..79
#pragma unroll
    for (int mt = 0; mt < 4; mt++)
#pragma unroll
        for (int nt = 0; nt < 4; nt++) {
            int col = nq * 32 + nt * 8 + cc;
            if (col < 80) {
                int r = mh * 64 + mt * 16 + rr;
                stage[r * 84 + col] = acc[mt][nt][0];
                stage[r * 84 + col + 1] = acc[mt][nt][1];
                stage[(r + 8) * 84 + col] = acc[mt][nt][2];
                stage[(r + 8) * 84 + col + 1] = acc[mt][nt][3];
            }
        }
    __syncthreads();
    for (int t = tid; t < 128 * 10; t += 256) {
        int nn = t / 10, c4 = t % 10;
        size_t gn = base + nn;
        if (gn < (size_t)n)
            *(float4*)(g_s + gn * 40 + c4 * 4) = *(float4*)(stage + nn * 84 + c4 * 4);
    }
    for (int t = tid; t < 128 * 20; t += 256) {
        int nn = t / 20, j = t % 20;
        size_t gn = base + nn;
        if (gn < (size_t)n) {
            __half2 h = __floats2half2_rn(stage[nn * 84 + 40 + 2 * j],
                                          stage[nn * 84 + 41 + 2 * j]);
            g_t[gn * 24 + j] = *(unsigned*)&h;
        }
    }
}

// ---------------- final aggregation: out[v] = s[v] + mean_t + b (fp16 gather) ----------------
__global__ __launch_bounds__(256)
void k_aggf(const float* __restrict__ b, float* __restrict__ out, int n) {
    grid_wait();
    int w = (blockIdx.x * 256 + threadIdx.x) >> 5;
    int lane = threadIdx.x & 31;
    if (w >= n) return;
    int beg = g_rp[w], end = g_rp[w + 1];

    const int l = min(lane, 19);
    float2 acc = make_float2(0.f, 0.f);
    for (int e = beg; e < end; e += 2) {
        int i1 = min(e + 1, end - 1);
        int u0 = g_col[e], u1 = g_col[i1];
        unsigned q0 = g_t[(size_t)u0 * 24 + l];
        unsigned q1 = g_t[(size_t)u1 * 24 + l];
        if (lane < 20) {
            float2 f0 = __half22float2(*(__half2*)&q0);
            acc.x += f0.x; acc.y += f0.y;
            if (e + 1 < end) {
                float2 f1 = __half22float2(*(__half2*)&q1);
                acc.x += f1.x; acc.y += f1.y;
            }
        }
    }
    if (lane < 20) {
        float inv = 1.0f / (float)max(end - beg, 1);
        float2 s = *(const float2*)(g_s + (size_t)w * 40 + 2 * lane);
        float2 bb = *(const float2*)(b + 2 * lane);
        float2 r;
        r.x = fmaf(acc.x, inv, s.x + bb.x);
        r.y = fmaf(acc.y, inv, s.y + bb.y);
        *(float2*)(out + (size_t)w * 40 + 2 * lane) = r;
    }
}

// ---------------- PDL launch helper ----------------
template <typename K, typename... Args>
static void launch_pdl(K kern, int grid, int block, size_t smem, Args... args) {
    cudaLaunchConfig_t cfg = {};
    cfg.gridDim = dim3(grid, 1, 1);
    cfg.blockDim = dim3(block, 1, 1);
    cfg.dynamicSmemBytes = smem;
    cfg.stream = 0;
    cudaLaunchAttribute attr[1];
    attr[0].id = cudaLaunchAttributeProgrammaticStreamSerialization;
    attr[0].val.programmaticStreamSerializationAllowed = 1;
    cfg.attrs = attr;
    cfg.numAttrs = 1;
    cudaLaunchKernelEx(&cfg, kern, args...);
}

// ---------------- launch ----------------
extern "C" void kernel_launch(void* const* d_in, const int* in_sizes, int n_in,
                              void* d_out, int out_size) {
    const float* x   = (const float*)d_in[0];
    const int*   src = (const int*)d_in[1];
    const int*   dst = (const int*)d_in[2];
    const float* ws1 = (const float*)d_in[3];
    const float* wn1 = (const float*)d_in[4];
    const float* b1  = (const float*)d_in[5];
    const float* ws2 = (const float*)d_in[6];
    const float* wn2 = (const float*)d_in[7];
    const float* b2  = (const float*)d_in[8];
    const float* ws3 = (const float*)d_in[9];
    const float* wn3 = (const float*)d_in[10];
    const float* b3  = (const float*)d_in[11];
    const float* ws4 = (const float*)d_in[12];
    const float* wn4 = (const float*)d_in[13];
    const float* b4  = (const float*)d_in[14];

    const int n = in_sizes[0] / 128;
    const int E = in_sizes[1];
    const int tiles = (n + 127) / 128;

    const int SMEM = 2 * 32768;
    cudaFuncSetAttribute(k_gemm_hid, cudaFuncAttributeMaxDynamicSharedMemorySize, SMEM);
    cudaFuncSetAttribute(k_gemm_fin, cudaFuncAttributeMaxDynamicSharedMemorySize, SMEM);

    uint4* pB;
    cudaGetSymbolAddress((void**)&pB, g_B);

    // fork: CSR chain on a side stream, overlapped with preps
    cudaStream_t s2;
    cudaStreamCreateWithFlags(&s2, cudaStreamNonBlocking);
    cudaEvent_t evFork, evJoin;
    cudaEventCreateWithFlags(&evFork, cudaEventDisableTiming);
    cudaEventCreateWithFlags(&evJoin, cudaEventDisableTiming);

    cudaEventRecord(evFork, 0);
    cudaStreamWaitEvent(s2, evFork, 0);

    k_zero_deg<<<(n + 255) / 256, 256, 0, s2>>>(n);
    k_count<<<(E + 255) / 256, 256, 0, s2>>>(dst, E);
    int nb = (n + 511) / 512;
    k_scan1<<<nb, 512, 0, s2>>>(n);
    k_scan3b<<<nb, 512, 0, s2>>>(n, E, nb);
    k_scatter<<<(E + 255) / 256, 256, 0, s2>>>(src, dst, E);
    cudaEventRecord(evJoin, s2);

    k_prep_all<<<64 + (n * 32 + 255) / 256, 256>>>(x, ws1, wn1, ws2, wn2,
                                                   ws3, wn3, ws4, wn4, n);
    cudaStreamWaitEvent(0, evJoin, 0);

    const int ga = (n + 7) / 8;

    // L1..L3: aggm triggers; gemm (PDL) overlaps its h-chunk phase with aggm tail
    k_aggm<<<ga, 256>>>(n);
    launch_pdl(k_gemm_hid, tiles, 256, (size_t)SMEM, (const uint4*)(pB + 0 * 4096), b1, n);
    k_aggm<<<ga, 256>>>(n);
    launch_pdl(k_gemm_hid, tiles, 256, (size_t)SMEM, (const uint4*)(pB + 1 * 4096), b2, n);
    k_aggm<<<ga, 256>>>(n);
    launch_pdl(k_gemm_hid, tiles, 256, (size_t)SMEM, (const uint4*)(pB + 2 * 4096), b3, n);
    // L4 + final gather
    launch_pdl(k_gemm_fin, tiles, 256, (size_t)SMEM, (const uint4*)(pB + 3 * 4096), b4, n);
    launch_pdl(k_aggf, ga, 256, (size_t)0, (const float*)b4, (float*)d_out, n);

    cudaEventDestroy(evFork);
    cudaEventDestroy(evJoin);
    cudaStreamDestroy(s2);
}